// round 14
// baseline (speedup 1.0000x reference)
#include <cuda_runtime.h>
#include <math.h>
#include <cstdio>
#include <cstdlib>

// Problem constants
#define NN 50000
#define EE 600000
#define DD 128
#define TT 4
#define BB 2048
#define SL 16
#define CC 16

// SGEMM tiling
#define MT 128
#define NT 32
#define KC 16
#define NCHUNK (DD / KC)   // 8
#define ASTRIDE (MT + 4)   // 132

// scan config
#define SB 256
#define NSB ((NN + SB - 1) / SB)   // 196

typedef unsigned long long u64;

#define FMA_X2(d, a, b, c) \
    asm("fma.rn.f32x2 %0, %1, %2, %3;" : "=l"(d) : "l"(a), "l"(b), "l"(c))
#define DUP_X2(out, f) \
    asm("mov.b64 %0, {%1, %1};" : "=l"(out) : "r"(__float_as_int(f)))
#define UNPK_X2(lo_u, hi_u, in) \
    asm("mov.b64 {%0, %1}, %2;" : "=r"(lo_u), "=r"(hi_u) : "l"(in))

// ---------------- scratch (device globals) -----------------------------------
__device__ float g_dis[NN];
__device__ int   g_deg[NN];
__device__ int   g_off[NN + 1];
__device__ int   g_cur[NN];
__device__ int   g_part[SB];
__device__ int2  g_adjn[EE];           // {src, norm-bits}
__device__ unsigned char g_flag1[NN];  // ego nodes
__device__ unsigned char g_flag2[NN];  // egos + in-neighbor sources of egos
__device__ int   g_list[NN];
__device__ int   g_nlist;
__device__ float g_xw[NN * DD];
__device__ float g_accA[NN * DD];
__device__ float g_W0t[TT * DD * DD];
__device__ float g_b0t[TT * DD];

// ---------------- relevance marking -------------------------------------------
__global__ void k_mark_ego(const int* __restrict__ seqs) {
    int b = blockIdx.x * blockDim.x + threadIdx.x;
    if (b < BB) {
        int v = seqs[b * SL];
        if ((unsigned)v < NN) { g_flag1[v] = 1; g_flag2[v] = 1; }
    }
}

// fused: degree count (all edges, true normalization) + flag2 marking
__global__ void k_degmark(const int* __restrict__ edge) {
    int e = blockIdx.x * blockDim.x + threadIdx.x;
    if (e >= EE) return;
    int v = edge[EE + e];
    if ((unsigned)v < NN) {
        atomicAdd(&g_deg[v], 1);
        if (g_flag1[v]) {
            int u = edge[e];
            if ((unsigned)u < NN) g_flag2[u] = 1;
        }
    }
}

// ---------------- hierarchical scan (CSR offsets) -----------------------------
__global__ __launch_bounds__(SB) void k_part() {
    __shared__ int sh[SB];
    int idx = blockIdx.x * SB + threadIdx.x;
    int v = (idx < NN) ? g_deg[idx] : 0;
    sh[threadIdx.x] = v;
    __syncthreads();
    for (int d = SB / 2; d > 0; d >>= 1) {
        if (threadIdx.x < d) sh[threadIdx.x] += sh[threadIdx.x + d];
        __syncthreads();
    }
    if (threadIdx.x == 0) g_part[blockIdx.x] = sh[0];
}

__global__ __launch_bounds__(SB) void k_scanp() {
    __shared__ int sh[SB];
    int tid = threadIdx.x;
    int v = (tid < NSB) ? g_part[tid] : 0;
    sh[tid] = v;
    __syncthreads();
    for (int d = 1; d < SB; d <<= 1) {
        int t = (tid >= d) ? sh[tid - d] : 0;
        __syncthreads();
        sh[tid] += t;
        __syncthreads();
    }
    if (tid < NSB) g_part[tid] = sh[tid] - v;
    if (tid == NSB - 1) g_off[NN] = sh[tid];
}

__global__ __launch_bounds__(SB) void k_off() {
    __shared__ int sh[SB];
    int tid = threadIdx.x;
    int idx = blockIdx.x * SB + tid;
    int v = (idx < NN) ? g_deg[idx] : 0;
    sh[tid] = v;
    __syncthreads();
    for (int d = 1; d < SB; d <<= 1) {
        int t = (tid >= d) ? sh[tid - d] : 0;
        __syncthreads();
        sh[tid] += t;
        __syncthreads();
    }
    if (idx < NN) {
        int o = g_part[blockIdx.x] + sh[tid] - v;
        g_off[idx] = o;
        g_cur[idx] = o;
        g_dis[idx] = rsqrtf((float)v + 1.0f);   // +1 = self loop
    }
}

// ---------------- CSR fill (only rows whose dst is relevant) ------------------
__global__ void k_fillf(const int* __restrict__ edge) {
    int e = blockIdx.x * blockDim.x + threadIdx.x;
    if (e >= EE) return;
    int v = edge[EE + e];
    if ((unsigned)v >= NN || !g_flag2[v]) return;
    int u = edge[e];
    if ((unsigned)u >= NN) return;
    int pos = atomicAdd(&g_cur[v], 1);
    float nm = g_dis[u] * g_dis[v];
    g_adjn[pos] = make_int2(u, __float_as_int(nm));
}

// ---------------- compaction: atomic append (order irrelevant) ----------------
__global__ void k_femita() {
    int idx = blockIdx.x * blockDim.x + threadIdx.x;
    if (idx < NN && g_flag2[idx]) {
        int pos = atomicAdd(&g_nlist, 1);
        g_list[pos] = idx;
    }
}

// ---------------- packed-FMA inner product ------------------------------------
#define GEMM_COMPUTE(As_, Bs_, mB_, nB_)                                       \
    do {                                                                       \
        _Pragma("unroll")                                                      \
        for (int kk = 0; kk < KC; kk++) {                                      \
            ulonglong2 a01 = *(const ulonglong2*)&As_[kk][mB_];                \
            ulonglong2 a23 = *(const ulonglong2*)&As_[kk][mB_ + 4];            \
            float4 b4 = *(const float4*)&Bs_[kk][nB_];                         \
            u64 ap[4] = {a01.x, a01.y, a23.x, a23.y};                          \
            u64 bd[4];                                                         \
            DUP_X2(bd[0], b4.x); DUP_X2(bd[1], b4.y);                          \
            DUP_X2(bd[2], b4.z); DUP_X2(bd[3], b4.w);                          \
            _Pragma("unroll")                                                  \
            for (int rp = 0; rp < 4; rp++)                                     \
                _Pragma("unroll")                                              \
                for (int c = 0; c < 4; c++)                                    \
                    FMA_X2(acc2[rp][c], ap[rp], bd[c], acc2[rp][c]);           \
        }                                                                      \
    } while (0)

// ---------------- weight folding: W0t[t] = fcW[t] @ W0 ------------------------
__global__ __launch_bounds__(128) void k_wcomb(
    const float* __restrict__ fcW, const float* __restrict__ W0,
    float* __restrict__ W0t)
{
    __shared__ float As[KC][ASTRIDE];
    __shared__ float Bs[KC][NT];
    const int tid = threadIdx.x;
    const int t  = blockIdx.y;
    const int n0 = blockIdx.x * NT;
    const int mB = (tid >> 3) * 8;
    const int nB = (tid & 7) * 4;
    const int bk = tid >> 3;
    const int bn = (tid & 7) * 4;

    const float* __restrict__ in  = fcW + (size_t)t * DD * DD;
    float* __restrict__ out = W0t + (size_t)t * DD * DD;

    u64 acc2[4][4];
    #pragma unroll
    for (int rp = 0; rp < 4; rp++)
        #pragma unroll
        for (int c = 0; c < 4; c++) acc2[rp][c] = 0ULL;

    float4 ar[4], br;
    {
        const float4* p = (const float4*)(in + (size_t)tid * DD);
        ar[0] = p[0]; ar[1] = p[1]; ar[2] = p[2]; ar[3] = p[3];
        br = *(const float4*)(W0 + (size_t)bk * DD + n0 + bn);
    }
    #pragma unroll
    for (int ch = 0; ch < NCHUNK; ch++) {
        __syncthreads();
        #pragma unroll
        for (int q = 0; q < 4; q++) {
            As[q * 4 + 0][tid] = ar[q].x;
            As[q * 4 + 1][tid] = ar[q].y;
            As[q * 4 + 2][tid] = ar[q].z;
            As[q * 4 + 3][tid] = ar[q].w;
        }
        *(float4*)&Bs[bk][bn] = br;
        __syncthreads();
        if (ch + 1 < NCHUNK) {
            int kc = (ch + 1) * KC;
            const float4* p = (const float4*)(in + (size_t)tid * DD + kc);
            ar[0] = p[0]; ar[1] = p[1]; ar[2] = p[2]; ar[3] = p[3];
            br = *(const float4*)(W0 + (size_t)(kc + bk) * DD + n0 + bn);
        }
        GEMM_COMPUTE(As, Bs, mB, nB);
    }
    #pragma unroll
    for (int rp = 0; rp < 4; rp++) {
        unsigned lo[4], hi[4];
        #pragma unroll
        for (int c = 0; c < 4; c++) UNPK_X2(lo[c], hi[c], acc2[rp][c]);
        *(float4*)(out + (size_t)(mB + 2 * rp + 0) * DD + n0 + nB) =
            make_float4(__uint_as_float(lo[0]), __uint_as_float(lo[1]),
                        __uint_as_float(lo[2]), __uint_as_float(lo[3]));
        *(float4*)(out + (size_t)(mB + 2 * rp + 1) * DD + n0 + nB) =
            make_float4(__uint_as_float(hi[0]), __uint_as_float(hi[1]),
                        __uint_as_float(hi[2]), __uint_as_float(hi[3]));
    }
}

__global__ __launch_bounds__(DD) void k_bcomb(
    const float* __restrict__ fcB, const float* __restrict__ W0,
    float* __restrict__ b0t)
{
    __shared__ float b[DD];
    const int t = blockIdx.x, j = threadIdx.x;
    b[j] = fcB[t * DD + j];
    __syncthreads();
    float s = 0.f;
    #pragma unroll 8
    for (int i = 0; i < DD; i++) s += b[i] * W0[i * DD + j];
    b0t[t * DD + j] = s;
}

// ---------------- fused FC+layer0 GEMM (all rows, all cols) -------------------
__global__ __launch_bounds__(128) void k_fc2(
    const float* __restrict__ x, const int* __restrict__ node_type,
    const float* __restrict__ W0t, const float* __restrict__ b0t,
    float* __restrict__ xw_out)
{
    __shared__ float As[KC][ASTRIDE];
    __shared__ float Bs[KC][NT];
    const int tid = threadIdx.x;
    const int m0 = blockIdx.y * MT;
    const int n0 = blockIdx.x * NT;
    const int mB = (tid >> 3) * 8;
    const int nB = (tid & 7) * 4;
    const int  mload  = m0 + tid;
    const bool mvalid = (mload < NN);
    const int  bk = tid >> 3;
    const int  bn = (tid & 7) * 4;

    int t0 = node_type[m0];
    int mlast = m0 + MT - 1; if (mlast >= NN) mlast = NN - 1;
    int t1 = node_type[mlast];
    if ((unsigned)t0 >= TT) t0 = 0;
    if ((unsigned)t1 >= TT) t1 = TT - 1;

    float4 ar[4], br;

    for (int t = t0; t <= t1; t++) {
        const float* __restrict__ W = W0t + (size_t)t * DD * DD;

        u64 acc2[4][4];
        #pragma unroll
        for (int rp = 0; rp < 4; rp++)
            #pragma unroll
            for (int c = 0; c < 4; c++) acc2[rp][c] = 0ULL;

        if (mvalid) {
            const float4* p = (const float4*)(x + (size_t)mload * DD);
            ar[0] = p[0]; ar[1] = p[1]; ar[2] = p[2]; ar[3] = p[3];
        } else {
            ar[0] = ar[1] = ar[2] = ar[3] = make_float4(0.f, 0.f, 0.f, 0.f);
        }
        br = *(const float4*)(W + (size_t)bk * DD + n0 + bn);

        #pragma unroll
        for (int ch = 0; ch < NCHUNK; ch++) {
            __syncthreads();
            #pragma unroll
            for (int q = 0; q < 4; q++) {
                As[q * 4 + 0][tid] = ar[q].x;
                As[q * 4 + 1][tid] = ar[q].y;
                As[q * 4 + 2][tid] = ar[q].z;
                As[q * 4 + 3][tid] = ar[q].w;
            }
            *(float4*)&Bs[bk][bn] = br;
            __syncthreads();
            if (ch + 1 < NCHUNK) {
                int kc = (ch + 1) * KC;
                if (mvalid) {
                    const float4* p = (const float4*)(x + (size_t)mload * DD + kc);
                    ar[0] = p[0]; ar[1] = p[1]; ar[2] = p[2]; ar[3] = p[3];
                }
                br = *(const float4*)(W + (size_t)(kc + bk) * DD + n0 + bn);
            }
            GEMM_COMPUTE(As, Bs, mB, nB);
        }

        const float4 fb = *(const float4*)(b0t + (size_t)t * DD + n0 + nB);
        #pragma unroll
        for (int rp = 0; rp < 4; rp++) {
            unsigned lo[4], hi[4];
            #pragma unroll
            for (int c = 0; c < 4; c++) UNPK_X2(lo[c], hi[c], acc2[rp][c]);
            int mlo = m0 + mB + 2 * rp;
            if (mlo < NN && node_type[mlo] == t)
                *(float4*)(xw_out + (size_t)mlo * DD + n0 + nB) =
                    make_float4(__uint_as_float(lo[0]) + fb.x,
                                __uint_as_float(lo[1]) + fb.y,
                                __uint_as_float(lo[2]) + fb.z,
                                __uint_as_float(lo[3]) + fb.w);
            int mhi = mlo + 1;
            if (mhi < NN && node_type[mhi] == t)
                *(float4*)(xw_out + (size_t)mhi * DD + n0 + nB) =
                    make_float4(__uint_as_float(hi[0]) + fb.x,
                                __uint_as_float(hi[1]) + fb.y,
                                __uint_as_float(hi[2]) + fb.z,
                                __uint_as_float(hi[3]) + fb.w);
        }
        __syncthreads();
    }
}

// ---------------- layer-1 GEMM over HALF of the compacted list ----------------
__global__ __launch_bounds__(128) void k_sgemm_idx(
    const float* __restrict__ in, const float* __restrict__ bias,
    const float* __restrict__ W, float* __restrict__ xw_out, int phase)
{
    const int nl = g_nlist;
    const int h  = (nl + 1) >> 1;
    const int start = phase ? h : 0;
    const int end   = phase ? nl : h;
    const int m0 = start + blockIdx.y * MT;
    if (m0 >= end) return;

    __shared__ float As[KC][ASTRIDE];
    __shared__ float Bs[KC][NT];
    __shared__ int   rows[MT];
    const int tid = threadIdx.x;
    const int n0 = blockIdx.x * NT;
    const int mB = (tid >> 3) * 8;
    const int nB = (tid & 7) * 4;
    const int bk = tid >> 3;
    const int bn = (tid & 7) * 4;

    int myrow = -1;
    if (m0 + tid < end) myrow = g_list[m0 + tid];
    rows[tid] = myrow;
    const bool mvalid = (myrow >= 0);

    u64 acc2[4][4];
    #pragma unroll
    for (int rp = 0; rp < 4; rp++)
        #pragma unroll
        for (int c = 0; c < 4; c++) acc2[rp][c] = 0ULL;

    float4 ar[4], br;

    #define LOAD_A(kc_) do {                                                     \
        if (mvalid) {                                                            \
            const float4* _p = (const float4*)(in + (size_t)myrow * DD + (kc_)); \
            ar[0] = _p[0]; ar[1] = _p[1]; ar[2] = _p[2]; ar[3] = _p[3];          \
            _Pragma("unroll")                                                    \
            for (int q = 0; q < 4; q++) {                                        \
                float4 bb = *(const float4*)(bias + (kc_) + q * 4);              \
                ar[q].x = fmaxf(ar[q].x + bb.x, 0.f);                            \
                ar[q].y = fmaxf(ar[q].y + bb.y, 0.f);                            \
                ar[q].z = fmaxf(ar[q].z + bb.z, 0.f);                            \
                ar[q].w = fmaxf(ar[q].w + bb.w, 0.f);                            \
            }                                                                    \
        } else {                                                                 \
            ar[0] = ar[1] = ar[2] = ar[3] = make_float4(0.f, 0.f, 0.f, 0.f);     \
        }                                                                        \
    } while (0)

    LOAD_A(0);
    br = *(const float4*)(W + (size_t)bk * DD + n0 + bn);
    #pragma unroll
    for (int ch = 0; ch < NCHUNK; ch++) {
        __syncthreads();
        #pragma unroll
        for (int q = 0; q < 4; q++) {
            As[q * 4 + 0][tid] = ar[q].x;
            As[q * 4 + 1][tid] = ar[q].y;
            As[q * 4 + 2][tid] = ar[q].z;
            As[q * 4 + 3][tid] = ar[q].w;
        }
        *(float4*)&Bs[bk][bn] = br;
        __syncthreads();
        if (ch + 1 < NCHUNK) {
            int kc = (ch + 1) * KC;
            LOAD_A(kc);
            br = *(const float4*)(W + (size_t)(kc + bk) * DD + n0 + bn);
        }
        GEMM_COMPUTE(As, Bs, mB, nB);
    }
    #pragma unroll
    for (int rp = 0; rp < 4; rp++) {
        unsigned lo[4], hi[4];
        #pragma unroll
        for (int c = 0; c < 4; c++) UNPK_X2(lo[c], hi[c], acc2[rp][c]);
        int rlo = rows[mB + 2 * rp + 0];
        if (rlo >= 0)
            *(float4*)(xw_out + (size_t)rlo * DD + n0 + nB) =
                make_float4(__uint_as_float(lo[0]), __uint_as_float(lo[1]),
                            __uint_as_float(lo[2]), __uint_as_float(lo[3]));
        int rhi = rows[mB + 2 * rp + 1];
        if (rhi >= 0)
            *(float4*)(xw_out + (size_t)rhi * DD + n0 + nB) =
                make_float4(__uint_as_float(hi[0]), __uint_as_float(hi[1]),
                            __uint_as_float(hi[2]), __uint_as_float(hi[3]));
    }
    #undef LOAD_A
}

// ---------------- CSR gather over HALF of the compacted list ------------------
__global__ __launch_bounds__(256) void k_gather_l(
    const float* __restrict__ xw, float* __restrict__ acc, int phase)
{
    const int nl = g_nlist;
    const int h  = (nl + 1) >> 1;
    const int start = phase ? h : 0;
    const int end   = phase ? nl : h;
    const int w    = (blockIdx.x * 256 + threadIdx.x) >> 5;
    const int lane = threadIdx.x & 31;
    const int idx = start + w;
    if (idx >= end) return;
    const int wid = g_list[idx];

    const int s = g_off[wid];
    const int e = g_off[wid + 1];
    const float4* __restrict__ xw4 = (const float4*)xw;

    const float d  = g_dis[wid];
    float4 self = xw4[(size_t)wid * 32 + lane];
    const float d2 = d * d;
    float4 a = make_float4(self.x * d2, self.y * d2, self.z * d2, self.w * d2);

    int i = s;
    for (; i + 4 <= e; i += 4) {
        int2 p0 = g_adjn[i];
        int2 p1 = g_adjn[i + 1];
        int2 p2 = g_adjn[i + 2];
        int2 p3 = g_adjn[i + 3];
        float4 v0 = xw4[(size_t)p0.x * 32 + lane];
        float4 v1 = xw4[(size_t)p1.x * 32 + lane];
        float4 v2 = xw4[(size_t)p2.x * 32 + lane];
        float4 v3 = xw4[(size_t)p3.x * 32 + lane];
        float n0 = __int_as_float(p0.y), n1 = __int_as_float(p1.y);
        float n2 = __int_as_float(p2.y), n3 = __int_as_float(p3.y);
        a.x += v0.x * n0 + v1.x * n1 + v2.x * n2 + v3.x * n3;
        a.y += v0.y * n0 + v1.y * n1 + v2.y * n2 + v3.y * n3;
        a.z += v0.z * n0 + v1.z * n1 + v2.z * n2 + v3.z * n3;
        a.w += v0.w * n0 + v1.w * n1 + v2.w * n2 + v3.w * n3;
    }
    for (; i < e; i++) {
        int2 p = g_adjn[i];
        float n = __int_as_float(p.y);
        float4 v = xw4[(size_t)p.x * 32 + lane];
        a.x += v.x * n; a.y += v.y * n; a.z += v.z * n; a.w += v.w * n;
    }
    ((float4*)acc)[(size_t)wid * 32 + lane] = a;
}

// ---------------- fused ego-gather + prediction head --------------------------
__global__ __launch_bounds__(DD) void k_predg(
    const float* __restrict__ xw, const float* __restrict__ gbias,
    const int* __restrict__ seqs, const int* __restrict__ label,
    const float* __restrict__ predW, const float* __restrict__ predB,
    float* __restrict__ out, int out_size)
{
    __shared__ float h[DD];
    __shared__ int ego_s;
    const int b = blockIdx.x, tid = threadIdx.x;
    if (tid == 0) {
        int e = seqs[b * SL];
        ego_s = ((unsigned)e < NN) ? e : 0;
    }
    __syncthreads();
    const int ego = ego_s;

    const int s = g_off[ego];
    const int e = g_off[ego + 1];
    const float d = g_dis[ego];
    float a = xw[(size_t)ego * DD + tid] * d * d;

    int i = s;
    for (; i + 2 <= e; i += 2) {
        int2 p0 = g_adjn[i];
        int2 p1 = g_adjn[i + 1];
        float v0 = xw[(size_t)p0.x * DD + tid];
        float v1 = xw[(size_t)p1.x * DD + tid];
        a += v0 * __int_as_float(p0.y) + v1 * __int_as_float(p1.y);
    }
    if (i < e) {
        int2 p = g_adjn[i];
        a += xw[(size_t)p.x * DD + tid] * __int_as_float(p.y);
    }

    h[tid] = fmaxf(a + gbias[tid], 0.0f);
    __syncthreads();

    if (tid < CC) {
        float s2 = predB[tid];
        #pragma unroll
        for (int k = 0; k < DD; k++) s2 += h[k] * predW[k * CC + tid];
        out[b * CC + tid] = s2;
    }
    if (tid == CC && out_size >= BB * CC + BB)
        out[BB * CC + b] = (float)label[ego];
}

// ---------------- host side ----------------------------------------------------
static bool now_capturing() {
    cudaStreamCaptureStatus s1 = cudaStreamCaptureStatusNone;
    cudaStreamCaptureStatus s2 = cudaStreamCaptureStatusNone;
    cudaError_t e1 = cudaStreamIsCapturing((cudaStream_t)0, &s1);
    cudaError_t e2 = cudaStreamIsCapturing(cudaStreamPerThread, &s2);
    if (e1 != cudaSuccess || e2 != cudaSuccess) { cudaGetLastError(); return true; }
    return s1 != cudaStreamCaptureStatusNone || s2 != cudaStreamCaptureStatusNone;
}

extern "C" void kernel_launch(void* const* d_in, const int* in_sizes, int n_in,
                              void* d_out, int out_size)
{
    const float* x         = (const float*)d_in[0];
    const int*   label     = (const int*)  d_in[1];
    const int*   seqs      = (const int*)  d_in[2];
    const int*   edge      = (const int*)  d_in[3];
    const int*   node_type = (const int*)  d_in[4];
    const float* fcW       = (const float*)d_in[5];
    const float* fcB       = (const float*)d_in[6];
    const float* gcnW      = (const float*)d_in[7];
    const float* gcnB      = (const float*)d_in[8];
    const float* predW     = (const float*)d_in[12];
    const float* predB     = (const float*)d_in[13];
    float* out = (float*)d_out;

    float *xw = 0, *accA = 0, *W0t = 0, *b0t = 0;
    int *degp = 0, *nlp = 0;
    unsigned char *f1p = 0, *f2p = 0;
    cudaGetSymbolAddress((void**)&xw,   g_xw);
    cudaGetSymbolAddress((void**)&accA, g_accA);
    cudaGetSymbolAddress((void**)&W0t,  g_W0t);
    cudaGetSymbolAddress((void**)&b0t,  g_b0t);
    cudaGetSymbolAddress((void**)&degp, g_deg);
    cudaGetSymbolAddress((void**)&nlp,  g_nlist);
    cudaGetSymbolAddress((void**)&f1p,  g_flag1);
    cudaGetSymbolAddress((void**)&f2p,  g_flag2);

    const bool capturing = now_capturing();

    static cudaStream_t s2 = 0;
    static cudaEvent_t evs[4];   // 0:fork 1:fc2done 2:g0 3:g1
    static bool tried = false, evok = false;
    if (!tried && !capturing) {
        tried = true;
        bool ok = (cudaStreamCreateWithFlags(&s2, cudaStreamNonBlocking) == cudaSuccess);
        for (int i = 0; i < 4 && ok; i++)
            ok = (cudaEventCreateWithFlags(&evs[i], cudaEventDisableTiming) == cudaSuccess);
        evok = ok;
        cudaGetLastError();
    }
    const bool par = capturing && evok;
    cudaStream_t sc = par ? s2 : (cudaStream_t)0;

    const dim3 gemmGrid(DD / NT, (NN + MT - 1) / MT);   // (4, 391)
    const dim3 combGrid(DD / NT, TT);
    const int gatherBlocks = (NN * 32 + 255) / 256;     // worst case

    if (par) {
        cudaEventRecord(evs[0], 0);
        cudaStreamWaitEvent(s2, evs[0], 0);
    }

    // ---- fork branch (s2 when capturing): CSR + relevance ----
    cudaMemsetAsync(degp, 0, NN * sizeof(int), sc);
    cudaMemsetAsync(f1p, 0, NN, sc);
    cudaMemsetAsync(f2p, 0, NN, sc);
    cudaMemsetAsync(nlp, 0, sizeof(int), sc);
    k_mark_ego<<<(BB + 255) / 256, 256, 0, sc>>>(seqs);
    k_degmark <<<(EE + 255) / 256, 256, 0, sc>>>(edge);
    k_part  <<<NSB, SB, 0, sc>>>();
    k_scanp <<<1,   SB, 0, sc>>>();
    k_off   <<<NSB, SB, 0, sc>>>();
    k_fillf <<<(EE + 255) / 256, 256, 0, sc>>>(edge);
    k_femita<<<NSB, SB, 0, sc>>>();

    // ---- main branch: weight folding + fused FC/layer0 GEMM ----
    k_wcomb<<<combGrid, 128>>>(fcW, gcnW, W0t);
    k_bcomb<<<TT, DD>>>(fcB, gcnW, b0t);
    k_fc2<<<gemmGrid, 128>>>(x, node_type, W0t, b0t, xw);
    if (par) cudaEventRecord(evs[1], 0);

    // ---- gather0 halves on fork stream; sgemm halves on main (pipelined) ----
    if (par) cudaStreamWaitEvent(s2, evs[1], 0);
    k_gather_l<<<gatherBlocks, 256, 0, sc>>>(xw, accA, 0);
    if (par) cudaEventRecord(evs[2], s2);
    k_gather_l<<<gatherBlocks, 256, 0, sc>>>(xw, accA, 1);
    if (par) cudaEventRecord(evs[3], s2);

    if (par) cudaStreamWaitEvent((cudaStream_t)0, evs[2], 0);
    k_sgemm_idx<<<gemmGrid, 128>>>(accA, gcnB, gcnW + DD * DD, xw, 0);
    if (par) cudaStreamWaitEvent((cudaStream_t)0, evs[3], 0);
    k_sgemm_idx<<<gemmGrid, 128>>>(accA, gcnB, gcnW + DD * DD, xw, 1);

    // fused ego aggregation + head
    k_predg<<<BB, DD>>>(xw, gcnB + DD, seqs, label, predW, predB, out, out_size);

    if (capturing) return;

    // ---- light self-check (non-capture calls only; exits only on failure) ----
    cudaError_t esync = cudaDeviceSynchronize();
    if (esync != cudaSuccess) {
        fprintf(stderr, "HX sync error: %s\n", cudaGetErrorString(esync));
        exit(2);
    }
    static float o0[CC];
    cudaMemcpy(o0, out, CC * 4, cudaMemcpyDeviceToHost);
    float l1 = 0;
    bool finite = true;
    for (int c = 0; c < CC; c++) { l1 += fabsf(o0[c]); if (!isfinite(o0[c])) finite = false; }
    if (!finite || l1 < 1e-4f) {
        fprintf(stderr, "HX bad output l1=%g finite=%d\n", l1, finite);
        exit(2);
    }
    cudaGetLastError();
}

// round 15
// speedup vs baseline: 1.1487x; 1.1487x over previous
#include <cuda_runtime.h>
#include <math.h>
#include <cstdio>
#include <cstdlib>

// Problem constants
#define NN 50000
#define EE 600000
#define DD 128
#define TT 4
#define BB 2048
#define SL 16
#define CC 16

// SGEMM tiling
#define MT 128
#define NT 32
#define KC 16
#define NCHUNK (DD / KC)   // 8
#define ASTRIDE (MT + 4)   // 132

// scan config
#define SB 256
#define NSB ((NN + SB - 1) / SB)   // 196

typedef unsigned long long u64;

#define FMA_X2(d, a, b, c) \
    asm("fma.rn.f32x2 %0, %1, %2, %3;" : "=l"(d) : "l"(a), "l"(b), "l"(c))
#define DUP_X2(out, f) \
    asm("mov.b64 %0, {%1, %1};" : "=l"(out) : "r"(__float_as_int(f)))
#define UNPK_X2(lo_u, hi_u, in) \
    asm("mov.b64 {%0, %1}, %2;" : "=r"(lo_u), "=r"(hi_u) : "l"(in))

// ---------------- scratch (device globals) -----------------------------------
__device__ float g_dis[NN];
__device__ int   g_deg[NN];
__device__ int   g_off[NN + 1];
__device__ int   g_cur[NN];
__device__ int   g_part[SB];
__device__ int2  g_adjn[EE];           // {src, norm-bits}
__device__ unsigned char g_flag1[NN];  // ego nodes
__device__ unsigned char g_flag2[NN];  // egos + in-neighbor sources of egos
__device__ int   g_list[NN];
__device__ int   g_nlist;
__device__ float g_xw[NN * DD];
__device__ float g_accA[NN * DD];
__device__ float g_W0t[TT * DD * DD];
__device__ float g_b0t[TT * DD];

// ---------------- relevance marking -------------------------------------------
__global__ void k_mark_ego(const int* __restrict__ seqs) {
    int b = blockIdx.x * blockDim.x + threadIdx.x;
    if (b < BB) {
        int v = seqs[b * SL];
        if ((unsigned)v < NN) { g_flag1[v] = 1; g_flag2[v] = 1; }
    }
}

// fused: degree count (all edges, true normalization) + flag2 marking
__global__ void k_degmark(const int* __restrict__ edge) {
    int e = blockIdx.x * blockDim.x + threadIdx.x;
    if (e >= EE) return;
    int v = edge[EE + e];
    if ((unsigned)v < NN) {
        atomicAdd(&g_deg[v], 1);
        if (g_flag1[v]) {
            int u = edge[e];
            if ((unsigned)u < NN) g_flag2[u] = 1;
        }
    }
}

// ---------------- hierarchical scan (CSR offsets) -----------------------------
__global__ __launch_bounds__(SB) void k_part() {
    __shared__ int sh[SB];
    int idx = blockIdx.x * SB + threadIdx.x;
    int v = (idx < NN) ? g_deg[idx] : 0;
    sh[threadIdx.x] = v;
    __syncthreads();
    for (int d = SB / 2; d > 0; d >>= 1) {
        if (threadIdx.x < d) sh[threadIdx.x] += sh[threadIdx.x + d];
        __syncthreads();
    }
    if (threadIdx.x == 0) g_part[blockIdx.x] = sh[0];
}

__global__ __launch_bounds__(SB) void k_scanp() {
    __shared__ int sh[SB];
    int tid = threadIdx.x;
    int v = (tid < NSB) ? g_part[tid] : 0;
    sh[tid] = v;
    __syncthreads();
    for (int d = 1; d < SB; d <<= 1) {
        int t = (tid >= d) ? sh[tid - d] : 0;
        __syncthreads();
        sh[tid] += t;
        __syncthreads();
    }
    if (tid < NSB) g_part[tid] = sh[tid] - v;
    if (tid == NSB - 1) g_off[NN] = sh[tid];
}

__global__ __launch_bounds__(SB) void k_off() {
    __shared__ int sh[SB];
    int tid = threadIdx.x;
    int idx = blockIdx.x * SB + tid;
    int v = (idx < NN) ? g_deg[idx] : 0;
    sh[tid] = v;
    __syncthreads();
    for (int d = 1; d < SB; d <<= 1) {
        int t = (tid >= d) ? sh[tid - d] : 0;
        __syncthreads();
        sh[tid] += t;
        __syncthreads();
    }
    if (idx < NN) {
        int o = g_part[blockIdx.x] + sh[tid] - v;
        g_off[idx] = o;
        g_cur[idx] = o;
        g_dis[idx] = rsqrtf((float)v + 1.0f);   // +1 = self loop
    }
}

// ---------------- CSR fill (only rows whose dst is relevant) ------------------
__global__ void k_fillf(const int* __restrict__ edge) {
    int e = blockIdx.x * blockDim.x + threadIdx.x;
    if (e >= EE) return;
    int v = edge[EE + e];
    if ((unsigned)v >= NN || !g_flag2[v]) return;
    int u = edge[e];
    if ((unsigned)u >= NN) return;
    int pos = atomicAdd(&g_cur[v], 1);
    float nm = g_dis[u] * g_dis[v];
    g_adjn[pos] = make_int2(u, __float_as_int(nm));
}

// ---------------- compaction: atomic append (order irrelevant) ----------------
__global__ void k_femita() {
    int idx = blockIdx.x * blockDim.x + threadIdx.x;
    if (idx < NN && g_flag2[idx]) {
        int pos = atomicAdd(&g_nlist, 1);
        g_list[pos] = idx;
    }
}

// ---------------- packed-FMA inner product ------------------------------------
#define GEMM_COMPUTE(As_, Bs_, mB_, nB_)                                       \
    do {                                                                       \
        _Pragma("unroll")                                                      \
        for (int kk = 0; kk < KC; kk++) {                                      \
            ulonglong2 a01 = *(const ulonglong2*)&As_[kk][mB_];                \
            ulonglong2 a23 = *(const ulonglong2*)&As_[kk][mB_ + 4];            \
            float4 b4 = *(const float4*)&Bs_[kk][nB_];                         \
            u64 ap[4] = {a01.x, a01.y, a23.x, a23.y};                          \
            u64 bd[4];                                                         \
            DUP_X2(bd[0], b4.x); DUP_X2(bd[1], b4.y);                          \
            DUP_X2(bd[2], b4.z); DUP_X2(bd[3], b4.w);                          \
            _Pragma("unroll")                                                  \
            for (int rp = 0; rp < 4; rp++)                                     \
                _Pragma("unroll")                                              \
                for (int c = 0; c < 4; c++)                                    \
                    FMA_X2(acc2[rp][c], ap[rp], bd[c], acc2[rp][c]);           \
        }                                                                      \
    } while (0)

// ---------------- weight folding: W0t[t] = fcW[t] @ W0 ------------------------
__global__ __launch_bounds__(128) void k_wcomb(
    const float* __restrict__ fcW, const float* __restrict__ W0,
    float* __restrict__ W0t)
{
    __shared__ float As[KC][ASTRIDE];
    __shared__ float Bs[KC][NT];
    const int tid = threadIdx.x;
    const int t  = blockIdx.y;
    const int n0 = blockIdx.x * NT;
    const int mB = (tid >> 3) * 8;
    const int nB = (tid & 7) * 4;
    const int bk = tid >> 3;
    const int bn = (tid & 7) * 4;

    const float* __restrict__ in  = fcW + (size_t)t * DD * DD;
    float* __restrict__ out = W0t + (size_t)t * DD * DD;

    u64 acc2[4][4];
    #pragma unroll
    for (int rp = 0; rp < 4; rp++)
        #pragma unroll
        for (int c = 0; c < 4; c++) acc2[rp][c] = 0ULL;

    float4 ar[4], br;
    {
        const float4* p = (const float4*)(in + (size_t)tid * DD);
        ar[0] = p[0]; ar[1] = p[1]; ar[2] = p[2]; ar[3] = p[3];
        br = *(const float4*)(W0 + (size_t)bk * DD + n0 + bn);
    }
    #pragma unroll
    for (int ch = 0; ch < NCHUNK; ch++) {
        __syncthreads();
        #pragma unroll
        for (int q = 0; q < 4; q++) {
            As[q * 4 + 0][tid] = ar[q].x;
            As[q * 4 + 1][tid] = ar[q].y;
            As[q * 4 + 2][tid] = ar[q].z;
            As[q * 4 + 3][tid] = ar[q].w;
        }
        *(float4*)&Bs[bk][bn] = br;
        __syncthreads();
        if (ch + 1 < NCHUNK) {
            int kc = (ch + 1) * KC;
            const float4* p = (const float4*)(in + (size_t)tid * DD + kc);
            ar[0] = p[0]; ar[1] = p[1]; ar[2] = p[2]; ar[3] = p[3];
            br = *(const float4*)(W0 + (size_t)(kc + bk) * DD + n0 + bn);
        }
        GEMM_COMPUTE(As, Bs, mB, nB);
    }
    #pragma unroll
    for (int rp = 0; rp < 4; rp++) {
        unsigned lo[4], hi[4];
        #pragma unroll
        for (int c = 0; c < 4; c++) UNPK_X2(lo[c], hi[c], acc2[rp][c]);
        *(float4*)(out + (size_t)(mB + 2 * rp + 0) * DD + n0 + nB) =
            make_float4(__uint_as_float(lo[0]), __uint_as_float(lo[1]),
                        __uint_as_float(lo[2]), __uint_as_float(lo[3]));
        *(float4*)(out + (size_t)(mB + 2 * rp + 1) * DD + n0 + nB) =
            make_float4(__uint_as_float(hi[0]), __uint_as_float(hi[1]),
                        __uint_as_float(hi[2]), __uint_as_float(hi[3]));
    }
}

__global__ __launch_bounds__(DD) void k_bcomb(
    const float* __restrict__ fcB, const float* __restrict__ W0,
    float* __restrict__ b0t)
{
    __shared__ float b[DD];
    const int t = blockIdx.x, j = threadIdx.x;
    b[j] = fcB[t * DD + j];
    __syncthreads();
    float s = 0.f;
    #pragma unroll 8
    for (int i = 0; i < DD; i++) s += b[i] * W0[i * DD + j];
    b0t[t * DD + j] = s;
}

// ---------------- fused FC+layer0 GEMM (all rows, all cols) -------------------
__global__ __launch_bounds__(128) void k_fc2(
    const float* __restrict__ x, const int* __restrict__ node_type,
    const float* __restrict__ W0t, const float* __restrict__ b0t,
    float* __restrict__ xw_out)
{
    __shared__ float As[KC][ASTRIDE];
    __shared__ float Bs[KC][NT];
    const int tid = threadIdx.x;
    const int m0 = blockIdx.y * MT;
    const int n0 = blockIdx.x * NT;
    const int mB = (tid >> 3) * 8;
    const int nB = (tid & 7) * 4;
    const int  mload  = m0 + tid;
    const bool mvalid = (mload < NN);
    const int  bk = tid >> 3;
    const int  bn = (tid & 7) * 4;

    int t0 = node_type[m0];
    int mlast = m0 + MT - 1; if (mlast >= NN) mlast = NN - 1;
    int t1 = node_type[mlast];
    if ((unsigned)t0 >= TT) t0 = 0;
    if ((unsigned)t1 >= TT) t1 = TT - 1;

    float4 ar[4], br;

    for (int t = t0; t <= t1; t++) {
        const float* __restrict__ W = W0t + (size_t)t * DD * DD;

        u64 acc2[4][4];
        #pragma unroll
        for (int rp = 0; rp < 4; rp++)
            #pragma unroll
            for (int c = 0; c < 4; c++) acc2[rp][c] = 0ULL;

        if (mvalid) {
            const float4* p = (const float4*)(x + (size_t)mload * DD);
            ar[0] = p[0]; ar[1] = p[1]; ar[2] = p[2]; ar[3] = p[3];
        } else {
            ar[0] = ar[1] = ar[2] = ar[3] = make_float4(0.f, 0.f, 0.f, 0.f);
        }
        br = *(const float4*)(W + (size_t)bk * DD + n0 + bn);

        #pragma unroll
        for (int ch = 0; ch < NCHUNK; ch++) {
            __syncthreads();
            #pragma unroll
            for (int q = 0; q < 4; q++) {
                As[q * 4 + 0][tid] = ar[q].x;
                As[q * 4 + 1][tid] = ar[q].y;
                As[q * 4 + 2][tid] = ar[q].z;
                As[q * 4 + 3][tid] = ar[q].w;
            }
            *(float4*)&Bs[bk][bn] = br;
            __syncthreads();
            if (ch + 1 < NCHUNK) {
                int kc = (ch + 1) * KC;
                if (mvalid) {
                    const float4* p = (const float4*)(x + (size_t)mload * DD + kc);
                    ar[0] = p[0]; ar[1] = p[1]; ar[2] = p[2]; ar[3] = p[3];
                }
                br = *(const float4*)(W + (size_t)(kc + bk) * DD + n0 + bn);
            }
            GEMM_COMPUTE(As, Bs, mB, nB);
        }

        const float4 fb = *(const float4*)(b0t + (size_t)t * DD + n0 + nB);
        #pragma unroll
        for (int rp = 0; rp < 4; rp++) {
            unsigned lo[4], hi[4];
            #pragma unroll
            for (int c = 0; c < 4; c++) UNPK_X2(lo[c], hi[c], acc2[rp][c]);
            int mlo = m0 + mB + 2 * rp;
            if (mlo < NN && node_type[mlo] == t)
                *(float4*)(xw_out + (size_t)mlo * DD + n0 + nB) =
                    make_float4(__uint_as_float(lo[0]) + fb.x,
                                __uint_as_float(lo[1]) + fb.y,
                                __uint_as_float(lo[2]) + fb.z,
                                __uint_as_float(lo[3]) + fb.w);
            int mhi = mlo + 1;
            if (mhi < NN && node_type[mhi] == t)
                *(float4*)(xw_out + (size_t)mhi * DD + n0 + nB) =
                    make_float4(__uint_as_float(hi[0]) + fb.x,
                                __uint_as_float(hi[1]) + fb.y,
                                __uint_as_float(hi[2]) + fb.z,
                                __uint_as_float(hi[3]) + fb.w);
        }
        __syncthreads();
    }
}

// ---------------- layer-1 GEMM over COMPACTED rows (monolithic) ---------------
__global__ __launch_bounds__(128) void k_sgemm_idx(
    const float* __restrict__ in, const float* __restrict__ bias,
    const float* __restrict__ W, float* __restrict__ xw_out)
{
    const int nlist = g_nlist;
    const int m0 = blockIdx.y * MT;
    if (m0 >= nlist) return;

    __shared__ float As[KC][ASTRIDE];
    __shared__ float Bs[KC][NT];
    __shared__ int   rows[MT];
    const int tid = threadIdx.x;
    const int n0 = blockIdx.x * NT;
    const int mB = (tid >> 3) * 8;
    const int nB = (tid & 7) * 4;
    const int bk = tid >> 3;
    const int bn = (tid & 7) * 4;

    int myrow = -1;
    if (m0 + tid < nlist) myrow = g_list[m0 + tid];
    rows[tid] = myrow;
    const bool mvalid = (myrow >= 0);

    u64 acc2[4][4];
    #pragma unroll
    for (int rp = 0; rp < 4; rp++)
        #pragma unroll
        for (int c = 0; c < 4; c++) acc2[rp][c] = 0ULL;

    float4 ar[4], br;

    #define LOAD_A(kc_) do {                                                     \
        if (mvalid) {                                                            \
            const float4* _p = (const float4*)(in + (size_t)myrow * DD + (kc_)); \
            ar[0] = _p[0]; ar[1] = _p[1]; ar[2] = _p[2]; ar[3] = _p[3];          \
            _Pragma("unroll")                                                    \
            for (int q = 0; q < 4; q++) {                                        \
                float4 bb = *(const float4*)(bias + (kc_) + q * 4);              \
                ar[q].x = fmaxf(ar[q].x + bb.x, 0.f);                            \
                ar[q].y = fmaxf(ar[q].y + bb.y, 0.f);                            \
                ar[q].z = fmaxf(ar[q].z + bb.z, 0.f);                            \
                ar[q].w = fmaxf(ar[q].w + bb.w, 0.f);                            \
            }                                                                    \
        } else {                                                                 \
            ar[0] = ar[1] = ar[2] = ar[3] = make_float4(0.f, 0.f, 0.f, 0.f);     \
        }                                                                        \
    } while (0)

    LOAD_A(0);
    br = *(const float4*)(W + (size_t)bk * DD + n0 + bn);
    #pragma unroll
    for (int ch = 0; ch < NCHUNK; ch++) {
        __syncthreads();
        #pragma unroll
        for (int q = 0; q < 4; q++) {
            As[q * 4 + 0][tid] = ar[q].x;
            As[q * 4 + 1][tid] = ar[q].y;
            As[q * 4 + 2][tid] = ar[q].z;
            As[q * 4 + 3][tid] = ar[q].w;
        }
        *(float4*)&Bs[bk][bn] = br;
        __syncthreads();
        if (ch + 1 < NCHUNK) {
            int kc = (ch + 1) * KC;
            LOAD_A(kc);
            br = *(const float4*)(W + (size_t)(kc + bk) * DD + n0 + bn);
        }
        GEMM_COMPUTE(As, Bs, mB, nB);
    }
    #pragma unroll
    for (int rp = 0; rp < 4; rp++) {
        unsigned lo[4], hi[4];
        #pragma unroll
        for (int c = 0; c < 4; c++) UNPK_X2(lo[c], hi[c], acc2[rp][c]);
        int rlo = rows[mB + 2 * rp + 0];
        if (rlo >= 0)
            *(float4*)(xw_out + (size_t)rlo * DD + n0 + nB) =
                make_float4(__uint_as_float(lo[0]), __uint_as_float(lo[1]),
                            __uint_as_float(lo[2]), __uint_as_float(lo[3]));
        int rhi = rows[mB + 2 * rp + 1];
        if (rhi >= 0)
            *(float4*)(xw_out + (size_t)rhi * DD + n0 + nB) =
                make_float4(__uint_as_float(hi[0]), __uint_as_float(hi[1]),
                            __uint_as_float(hi[2]), __uint_as_float(hi[3]));
    }
    #undef LOAD_A
}

// ---------------- CSR gather over the compacted list --------------------------
__global__ __launch_bounds__(256) void k_gather_l(
    const float* __restrict__ xw, float* __restrict__ acc)
{
    const int w    = (blockIdx.x * 256 + threadIdx.x) >> 5;
    const int lane = threadIdx.x & 31;
    if (w >= g_nlist) return;
    const int wid = g_list[w];

    const int s = g_off[wid];
    const int e = g_off[wid + 1];
    const float4* __restrict__ xw4 = (const float4*)xw;

    const float d  = g_dis[wid];
    float4 self = xw4[(size_t)wid * 32 + lane];
    const float d2 = d * d;
    float4 a = make_float4(self.x * d2, self.y * d2, self.z * d2, self.w * d2);

    int i = s;
    for (; i + 4 <= e; i += 4) {
        int2 p0 = g_adjn[i];
        int2 p1 = g_adjn[i + 1];
        int2 p2 = g_adjn[i + 2];
        int2 p3 = g_adjn[i + 3];
        float4 v0 = xw4[(size_t)p0.x * 32 + lane];
        float4 v1 = xw4[(size_t)p1.x * 32 + lane];
        float4 v2 = xw4[(size_t)p2.x * 32 + lane];
        float4 v3 = xw4[(size_t)p3.x * 32 + lane];
        float n0 = __int_as_float(p0.y), n1 = __int_as_float(p1.y);
        float n2 = __int_as_float(p2.y), n3 = __int_as_float(p3.y);
        a.x += v0.x * n0 + v1.x * n1 + v2.x * n2 + v3.x * n3;
        a.y += v0.y * n0 + v1.y * n1 + v2.y * n2 + v3.y * n3;
        a.z += v0.z * n0 + v1.z * n1 + v2.z * n2 + v3.z * n3;
        a.w += v0.w * n0 + v1.w * n1 + v2.w * n2 + v3.w * n3;
    }
    for (; i < e; i++) {
        int2 p = g_adjn[i];
        float n = __int_as_float(p.y);
        float4 v = xw4[(size_t)p.x * 32 + lane];
        a.x += v.x * n; a.y += v.y * n; a.z += v.z * n; a.w += v.w * n;
    }
    ((float4*)acc)[(size_t)wid * 32 + lane] = a;
}

// ---------------- fused ego-gather + prediction head --------------------------
__global__ __launch_bounds__(DD) void k_predg(
    const float* __restrict__ xw, const float* __restrict__ gbias,
    const int* __restrict__ seqs, const int* __restrict__ label,
    const float* __restrict__ predW, const float* __restrict__ predB,
    float* __restrict__ out, int out_size)
{
    __shared__ float h[DD];
    __shared__ int ego_s;
    const int b = blockIdx.x, tid = threadIdx.x;
    if (tid == 0) {
        int e = seqs[b * SL];
        ego_s = ((unsigned)e < NN) ? e : 0;
    }
    __syncthreads();
    const int ego = ego_s;

    const int s = g_off[ego];
    const int e = g_off[ego + 1];
    const float d = g_dis[ego];
    float a = xw[(size_t)ego * DD + tid] * d * d;

    int i = s;
    for (; i + 2 <= e; i += 2) {
        int2 p0 = g_adjn[i];
        int2 p1 = g_adjn[i + 1];
        float v0 = xw[(size_t)p0.x * DD + tid];
        float v1 = xw[(size_t)p1.x * DD + tid];
        a += v0 * __int_as_float(p0.y) + v1 * __int_as_float(p1.y);
    }
    if (i < e) {
        int2 p = g_adjn[i];
        a += xw[(size_t)p.x * DD + tid] * __int_as_float(p.y);
    }

    h[tid] = fmaxf(a + gbias[tid], 0.0f);
    __syncthreads();

    if (tid < CC) {
        float s2 = predB[tid];
        #pragma unroll
        for (int k = 0; k < DD; k++) s2 += h[k] * predW[k * CC + tid];
        out[b * CC + tid] = s2;
    }
    if (tid == CC && out_size >= BB * CC + BB)
        out[BB * CC + b] = (float)label[ego];
}

// ---------------- host side ----------------------------------------------------
static bool now_capturing() {
    cudaStreamCaptureStatus s1 = cudaStreamCaptureStatusNone;
    cudaStreamCaptureStatus s2 = cudaStreamCaptureStatusNone;
    cudaError_t e1 = cudaStreamIsCapturing((cudaStream_t)0, &s1);
    cudaError_t e2 = cudaStreamIsCapturing(cudaStreamPerThread, &s2);
    if (e1 != cudaSuccess || e2 != cudaSuccess) { cudaGetLastError(); return true; }
    return s1 != cudaStreamCaptureStatusNone || s2 != cudaStreamCaptureStatusNone;
}

extern "C" void kernel_launch(void* const* d_in, const int* in_sizes, int n_in,
                              void* d_out, int out_size)
{
    const float* x         = (const float*)d_in[0];
    const int*   label     = (const int*)  d_in[1];
    const int*   seqs      = (const int*)  d_in[2];
    const int*   edge      = (const int*)  d_in[3];
    const int*   node_type = (const int*)  d_in[4];
    const float* fcW       = (const float*)d_in[5];
    const float* fcB       = (const float*)d_in[6];
    const float* gcnW      = (const float*)d_in[7];
    const float* gcnB      = (const float*)d_in[8];
    const float* predW     = (const float*)d_in[12];
    const float* predB     = (const float*)d_in[13];
    float* out = (float*)d_out;

    float *xw = 0, *accA = 0, *W0t = 0, *b0t = 0;
    int *degp = 0, *nlp = 0;
    unsigned char *f1p = 0, *f2p = 0;
    cudaGetSymbolAddress((void**)&xw,   g_xw);
    cudaGetSymbolAddress((void**)&accA, g_accA);
    cudaGetSymbolAddress((void**)&W0t,  g_W0t);
    cudaGetSymbolAddress((void**)&b0t,  g_b0t);
    cudaGetSymbolAddress((void**)&degp, g_deg);
    cudaGetSymbolAddress((void**)&nlp,  g_nlist);
    cudaGetSymbolAddress((void**)&f1p,  g_flag1);
    cudaGetSymbolAddress((void**)&f2p,  g_flag2);

    const bool capturing = now_capturing();

    static cudaStream_t s_csr = 0;
    static cudaEvent_t  eFork = 0, eCsr = 0;
    static bool tried = false;
    if (!tried && !capturing) {
        tried = true;
        if (cudaStreamCreateWithFlags(&s_csr, cudaStreamNonBlocking) != cudaSuccess) s_csr = 0;
        if (cudaEventCreateWithFlags(&eFork, cudaEventDisableTiming) != cudaSuccess) eFork = 0;
        if (cudaEventCreateWithFlags(&eCsr,  cudaEventDisableTiming) != cudaSuccess) eCsr = 0;
        cudaGetLastError();
    }
    const bool par = capturing && s_csr && eFork && eCsr;
    cudaStream_t sc = par ? s_csr : (cudaStream_t)0;

    const dim3 gemmGrid(DD / NT, (NN + MT - 1) / MT);   // (4, 391)
    const dim3 combGrid(DD / NT, TT);
    const int gatherBlocks = (NN * 32 + 255) / 256;     // worst case; excess exits

    if (par) {
        cudaEventRecord(eFork, 0);
        cudaStreamWaitEvent(s_csr, eFork, 0);
    }

    // ---- fork branch: CSR + relevance (slimmed) ----
    cudaMemsetAsync(degp, 0, NN * sizeof(int), sc);
    cudaMemsetAsync(f1p, 0, NN, sc);
    cudaMemsetAsync(f2p, 0, NN, sc);
    cudaMemsetAsync(nlp, 0, sizeof(int), sc);
    k_mark_ego<<<(BB + 255) / 256, 256, 0, sc>>>(seqs);
    k_degmark <<<(EE + 255) / 256, 256, 0, sc>>>(edge);
    k_part  <<<NSB, SB, 0, sc>>>();
    k_scanp <<<1,   SB, 0, sc>>>();
    k_off   <<<NSB, SB, 0, sc>>>();
    k_fillf <<<(EE + 255) / 256, 256, 0, sc>>>(edge);
    k_femita<<<NSB, SB, 0, sc>>>();
    if (par) cudaEventRecord(eCsr, s_csr);

    // ---- main branch: weight folding + fused FC/layer0 GEMM ----
    k_wcomb<<<combGrid, 128>>>(fcW, gcnW, W0t);
    k_bcomb<<<TT, DD>>>(fcB, gcnW, b0t);
    k_fc2<<<gemmGrid, 128>>>(x, node_type, W0t, b0t, xw);

    if (par) cudaStreamWaitEvent((cudaStream_t)0, eCsr, 0);

    // serial join: gather0 -> layer-1 GEMM -> fused ego-gather+head
    k_gather_l <<<gatherBlocks, 256>>>(xw, accA);
    k_sgemm_idx<<<gemmGrid, 128>>>(accA, gcnB, gcnW + DD * DD, xw);
    k_predg<<<BB, DD>>>(xw, gcnB + DD, seqs, label, predW, predB, out, out_size);

    if (capturing) return;

    // ---- light self-check (non-capture calls only; exits only on failure) ----
    cudaError_t esync = cudaDeviceSynchronize();
    if (esync != cudaSuccess) {
        fprintf(stderr, "HX sync error: %s\n", cudaGetErrorString(esync));
        exit(2);
    }
    static float o0[CC];
    cudaMemcpy(o0, out, CC * 4, cudaMemcpyDeviceToHost);
    float l1 = 0;
    bool finite = true;
    for (int c = 0; c < CC; c++) { l1 += fabsf(o0[c]); if (!isfinite(o0[c])) finite = false; }
    if (!finite || l1 < 1e-4f) {
        fprintf(stderr, "HX bad output l1=%g finite=%d\n", l1, finite);
        exit(2);
    }
    cudaGetLastError();
}

// round 16
// speedup vs baseline: 1.1614x; 1.0110x over previous
#include <cuda_runtime.h>
#include <math.h>
#include <cstdio>
#include <cstdlib>

// Problem constants
#define NN 50000
#define EE 600000
#define DD 128
#define TT 4
#define BB 2048
#define SL 16
#define CC 16

// SGEMM tiling
#define MT 128
#define NT 32
#define KC 16
#define NCHUNK (DD / KC)   // 8
#define ASTRIDE (MT + 4)   // 132

// scan config
#define SB 256
#define NSB ((NN + SB - 1) / SB)   // 196

typedef unsigned long long u64;

#define FMA_X2(d, a, b, c) \
    asm("fma.rn.f32x2 %0, %1, %2, %3;" : "=l"(d) : "l"(a), "l"(b), "l"(c))
#define DUP_X2(out, f) \
    asm("mov.b64 %0, {%1, %1};" : "=l"(out) : "r"(__float_as_int(f)))
#define UNPK_X2(lo_u, hi_u, in) \
    asm("mov.b64 {%0, %1}, %2;" : "=r"(lo_u), "=r"(hi_u) : "l"(in))

// ---------------- scratch (device globals) -----------------------------------
__device__ float g_dis[NN];
__device__ int   g_deg[NN];
__device__ int   g_off[NN + 1];
__device__ int   g_cur[NN];
__device__ int   g_part[SB];
__device__ int2  g_adjn[EE];           // {src, norm-bits}
__device__ unsigned char g_flag1[NN];  // ego nodes
__device__ unsigned char g_flag2[NN];  // egos + in-neighbor sources of egos
__device__ int   g_list[NN];
__device__ int   g_nlist;
__device__ float g_xw[NN * DD];
__device__ float g_accA[NN * DD];
__device__ float g_W0t[TT * DD * DD];
__device__ float g_b0t[TT * DD];

// ---------------- relevance marking -------------------------------------------
__global__ void k_mark_ego(const int* __restrict__ seqs) {
    int b = blockIdx.x * blockDim.x + threadIdx.x;
    if (b < BB) {
        int v = seqs[b * SL];
        if ((unsigned)v < NN) { g_flag1[v] = 1; g_flag2[v] = 1; }
    }
}

// fused: degree count (all edges, true normalization) + flag2 marking
__global__ void k_degmark(const int* __restrict__ edge) {
    int e = blockIdx.x * blockDim.x + threadIdx.x;
    if (e >= EE) return;
    int v = edge[EE + e];
    if ((unsigned)v < NN) {
        atomicAdd(&g_deg[v], 1);
        if (g_flag1[v]) {
            int u = edge[e];
            if ((unsigned)u < NN) g_flag2[u] = 1;
        }
    }
}

// ---------------- hierarchical scan (CSR offsets) -----------------------------
__global__ __launch_bounds__(SB) void k_part() {
    __shared__ int sh[SB];
    int idx = blockIdx.x * SB + threadIdx.x;
    int v = (idx < NN) ? g_deg[idx] : 0;
    sh[threadIdx.x] = v;
    __syncthreads();
    for (int d = SB / 2; d > 0; d >>= 1) {
        if (threadIdx.x < d) sh[threadIdx.x] += sh[threadIdx.x + d];
        __syncthreads();
    }
    if (threadIdx.x == 0) g_part[blockIdx.x] = sh[0];
}

__global__ __launch_bounds__(SB) void k_scanp() {
    __shared__ int sh[SB];
    int tid = threadIdx.x;
    int v = (tid < NSB) ? g_part[tid] : 0;
    sh[tid] = v;
    __syncthreads();
    for (int d = 1; d < SB; d <<= 1) {
        int t = (tid >= d) ? sh[tid - d] : 0;
        __syncthreads();
        sh[tid] += t;
        __syncthreads();
    }
    if (tid < NSB) g_part[tid] = sh[tid] - v;
    if (tid == NSB - 1) g_off[NN] = sh[tid];
}

__global__ __launch_bounds__(SB) void k_off() {
    __shared__ int sh[SB];
    int tid = threadIdx.x;
    int idx = blockIdx.x * SB + tid;
    int v = (idx < NN) ? g_deg[idx] : 0;
    sh[tid] = v;
    __syncthreads();
    for (int d = 1; d < SB; d <<= 1) {
        int t = (tid >= d) ? sh[tid - d] : 0;
        __syncthreads();
        sh[tid] += t;
        __syncthreads();
    }
    if (idx < NN) {
        int o = g_part[blockIdx.x] + sh[tid] - v;
        g_off[idx] = o;
        g_cur[idx] = o;
        g_dis[idx] = rsqrtf((float)v + 1.0f);   // +1 = self loop
    }
}

// ---------------- CSR fill (only rows whose dst is relevant) ------------------
__global__ void k_fillf(const int* __restrict__ edge) {
    int e = blockIdx.x * blockDim.x + threadIdx.x;
    if (e >= EE) return;
    int v = edge[EE + e];
    if ((unsigned)v >= NN || !g_flag2[v]) return;
    int u = edge[e];
    if ((unsigned)u >= NN) return;
    int pos = atomicAdd(&g_cur[v], 1);
    float nm = g_dis[u] * g_dis[v];
    g_adjn[pos] = make_int2(u, __float_as_int(nm));
}

// ---------------- compaction: atomic append (order irrelevant) ----------------
__global__ void k_femita() {
    int idx = blockIdx.x * blockDim.x + threadIdx.x;
    if (idx < NN && g_flag2[idx]) {
        int pos = atomicAdd(&g_nlist, 1);
        g_list[pos] = idx;
    }
}

// ---------------- packed-FMA inner product ------------------------------------
#define GEMM_COMPUTE(As_, Bs_, mB_, nB_)                                       \
    do {                                                                       \
        _Pragma("unroll")                                                      \
        for (int kk = 0; kk < KC; kk++) {                                      \
            ulonglong2 a01 = *(const ulonglong2*)&As_[kk][mB_];                \
            ulonglong2 a23 = *(const ulonglong2*)&As_[kk][mB_ + 4];            \
            float4 b4 = *(const float4*)&Bs_[kk][nB_];                         \
            u64 ap[4] = {a01.x, a01.y, a23.x, a23.y};                          \
            u64 bd[4];                                                         \
            DUP_X2(bd[0], b4.x); DUP_X2(bd[1], b4.y);                          \
            DUP_X2(bd[2], b4.z); DUP_X2(bd[3], b4.w);                          \
            _Pragma("unroll")                                                  \
            for (int rp = 0; rp < 4; rp++)                                     \
                _Pragma("unroll")                                              \
                for (int c = 0; c < 4; c++)                                    \
                    FMA_X2(acc2[rp][c], ap[rp], bd[c], acc2[rp][c]);           \
        }                                                                      \
    } while (0)

#define STORE_SMEM(Ab_, Bb_)                                                   \
    do {                                                                       \
        _Pragma("unroll")                                                      \
        for (int q = 0; q < 4; q++) {                                          \
            Ab_[q * 4 + 0][tid] = ar[q].x;                                     \
            Ab_[q * 4 + 1][tid] = ar[q].y;                                     \
            Ab_[q * 4 + 2][tid] = ar[q].z;                                     \
            Ab_[q * 4 + 3][tid] = ar[q].w;                                     \
        }                                                                      \
        *(float4*)&Bb_[bk][bn] = br;                                           \
    } while (0)

// ---------------- weight folding: W0t[t] = fcW[t] @ W0 ------------------------
__global__ __launch_bounds__(128) void k_wcomb(
    const float* __restrict__ fcW, const float* __restrict__ W0,
    float* __restrict__ W0t)
{
    __shared__ float As[2][KC][ASTRIDE];
    __shared__ float Bs[2][KC][NT];
    const int tid = threadIdx.x;
    const int t  = blockIdx.y;
    const int n0 = blockIdx.x * NT;
    const int mB = (tid >> 3) * 8;
    const int nB = (tid & 7) * 4;
    const int bk = tid >> 3;
    const int bn = (tid & 7) * 4;

    const float* __restrict__ in  = fcW + (size_t)t * DD * DD;
    float* __restrict__ out = W0t + (size_t)t * DD * DD;

    u64 acc2[4][4];
    #pragma unroll
    for (int rp = 0; rp < 4; rp++)
        #pragma unroll
        for (int c = 0; c < 4; c++) acc2[rp][c] = 0ULL;

    float4 ar[4], br;
    {
        const float4* p = (const float4*)(in + (size_t)tid * DD);
        ar[0] = p[0]; ar[1] = p[1]; ar[2] = p[2]; ar[3] = p[3];
        br = *(const float4*)(W0 + (size_t)bk * DD + n0 + bn);
    }
    STORE_SMEM(As[0], Bs[0]);
    __syncthreads();
    #pragma unroll
    for (int ch = 0; ch < NCHUNK; ch++) {
        const int cur = ch & 1;
        if (ch + 1 < NCHUNK) {
            int kc = (ch + 1) * KC;
            const float4* p = (const float4*)(in + (size_t)tid * DD + kc);
            ar[0] = p[0]; ar[1] = p[1]; ar[2] = p[2]; ar[3] = p[3];
            br = *(const float4*)(W0 + (size_t)(kc + bk) * DD + n0 + bn);
        }
        GEMM_COMPUTE(As[cur], Bs[cur], mB, nB);
        if (ch + 1 < NCHUNK) {
            STORE_SMEM(As[cur ^ 1], Bs[cur ^ 1]);
            __syncthreads();
        }
    }
    #pragma unroll
    for (int rp = 0; rp < 4; rp++) {
        unsigned lo[4], hi[4];
        #pragma unroll
        for (int c = 0; c < 4; c++) UNPK_X2(lo[c], hi[c], acc2[rp][c]);
        *(float4*)(out + (size_t)(mB + 2 * rp + 0) * DD + n0 + nB) =
            make_float4(__uint_as_float(lo[0]), __uint_as_float(lo[1]),
                        __uint_as_float(lo[2]), __uint_as_float(lo[3]));
        *(float4*)(out + (size_t)(mB + 2 * rp + 1) * DD + n0 + nB) =
            make_float4(__uint_as_float(hi[0]), __uint_as_float(hi[1]),
                        __uint_as_float(hi[2]), __uint_as_float(hi[3]));
    }
}

__global__ __launch_bounds__(DD) void k_bcomb(
    const float* __restrict__ fcB, const float* __restrict__ W0,
    float* __restrict__ b0t)
{
    __shared__ float b[DD];
    const int t = blockIdx.x, j = threadIdx.x;
    b[j] = fcB[t * DD + j];
    __syncthreads();
    float s = 0.f;
    #pragma unroll 8
    for (int i = 0; i < DD; i++) s += b[i] * W0[i * DD + j];
    b0t[t * DD + j] = s;
}

// ---------------- fused FC+layer0 GEMM (double-buffered) ----------------------
__global__ __launch_bounds__(128) void k_fc2(
    const float* __restrict__ x, const int* __restrict__ node_type,
    const float* __restrict__ W0t, const float* __restrict__ b0t,
    float* __restrict__ xw_out)
{
    __shared__ float As[2][KC][ASTRIDE];
    __shared__ float Bs[2][KC][NT];
    const int tid = threadIdx.x;
    const int m0 = blockIdx.y * MT;
    const int n0 = blockIdx.x * NT;
    const int mB = (tid >> 3) * 8;
    const int nB = (tid & 7) * 4;
    const int  mload  = m0 + tid;
    const bool mvalid = (mload < NN);
    const int  bk = tid >> 3;
    const int  bn = (tid & 7) * 4;

    int t0 = node_type[m0];
    int mlast = m0 + MT - 1; if (mlast >= NN) mlast = NN - 1;
    int t1 = node_type[mlast];
    if ((unsigned)t0 >= TT) t0 = 0;
    if ((unsigned)t1 >= TT) t1 = TT - 1;

    float4 ar[4], br;

    for (int t = t0; t <= t1; t++) {
        const float* __restrict__ W = W0t + (size_t)t * DD * DD;

        u64 acc2[4][4];
        #pragma unroll
        for (int rp = 0; rp < 4; rp++)
            #pragma unroll
            for (int c = 0; c < 4; c++) acc2[rp][c] = 0ULL;

        if (mvalid) {
            const float4* p = (const float4*)(x + (size_t)mload * DD);
            ar[0] = p[0]; ar[1] = p[1]; ar[2] = p[2]; ar[3] = p[3];
        } else {
            ar[0] = ar[1] = ar[2] = ar[3] = make_float4(0.f, 0.f, 0.f, 0.f);
        }
        br = *(const float4*)(W + (size_t)bk * DD + n0 + bn);
        STORE_SMEM(As[0], Bs[0]);
        __syncthreads();

        #pragma unroll
        for (int ch = 0; ch < NCHUNK; ch++) {
            const int cur = ch & 1;
            if (ch + 1 < NCHUNK) {
                int kc = (ch + 1) * KC;
                if (mvalid) {
                    const float4* p = (const float4*)(x + (size_t)mload * DD + kc);
                    ar[0] = p[0]; ar[1] = p[1]; ar[2] = p[2]; ar[3] = p[3];
                }
                br = *(const float4*)(W + (size_t)(kc + bk) * DD + n0 + bn);
            }
            GEMM_COMPUTE(As[cur], Bs[cur], mB, nB);
            if (ch + 1 < NCHUNK) {
                STORE_SMEM(As[cur ^ 1], Bs[cur ^ 1]);
                __syncthreads();
            }
        }

        const float4 fb = *(const float4*)(b0t + (size_t)t * DD + n0 + nB);
        #pragma unroll
        for (int rp = 0; rp < 4; rp++) {
            unsigned lo[4], hi[4];
            #pragma unroll
            for (int c = 0; c < 4; c++) UNPK_X2(lo[c], hi[c], acc2[rp][c]);
            int mlo = m0 + mB + 2 * rp;
            if (mlo < NN && node_type[mlo] == t)
                *(float4*)(xw_out + (size_t)mlo * DD + n0 + nB) =
                    make_float4(__uint_as_float(lo[0]) + fb.x,
                                __uint_as_float(lo[1]) + fb.y,
                                __uint_as_float(lo[2]) + fb.z,
                                __uint_as_float(lo[3]) + fb.w);
            int mhi = mlo + 1;
            if (mhi < NN && node_type[mhi] == t)
                *(float4*)(xw_out + (size_t)mhi * DD + n0 + nB) =
                    make_float4(__uint_as_float(hi[0]) + fb.x,
                                __uint_as_float(hi[1]) + fb.y,
                                __uint_as_float(hi[2]) + fb.z,
                                __uint_as_float(hi[3]) + fb.w);
        }
        __syncthreads();  // protect smem before next type pass restores buf 0
    }
}

// ---------------- layer-1 GEMM over COMPACTED rows (double-buffered) ----------
__global__ __launch_bounds__(128) void k_sgemm_idx(
    const float* __restrict__ in, const float* __restrict__ bias,
    const float* __restrict__ W, float* __restrict__ xw_out)
{
    const int nlist = g_nlist;
    const int m0 = blockIdx.y * MT;
    if (m0 >= nlist) return;

    __shared__ float As[2][KC][ASTRIDE];
    __shared__ float Bs[2][KC][NT];
    __shared__ int   rows[MT];
    const int tid = threadIdx.x;
    const int n0 = blockIdx.x * NT;
    const int mB = (tid >> 3) * 8;
    const int nB = (tid & 7) * 4;
    const int bk = tid >> 3;
    const int bn = (tid & 7) * 4;

    int myrow = -1;
    if (m0 + tid < nlist) myrow = g_list[m0 + tid];
    rows[tid] = myrow;
    const bool mvalid = (myrow >= 0);

    u64 acc2[4][4];
    #pragma unroll
    for (int rp = 0; rp < 4; rp++)
        #pragma unroll
        for (int c = 0; c < 4; c++) acc2[rp][c] = 0ULL;

    float4 ar[4], br;

    #define LOAD_A(kc_) do {                                                     \
        if (mvalid) {                                                            \
            const float4* _p = (const float4*)(in + (size_t)myrow * DD + (kc_)); \
            ar[0] = _p[0]; ar[1] = _p[1]; ar[2] = _p[2]; ar[3] = _p[3];          \
            _Pragma("unroll")                                                    \
            for (int q = 0; q < 4; q++) {                                        \
                float4 bb = *(const float4*)(bias + (kc_) + q * 4);              \
                ar[q].x = fmaxf(ar[q].x + bb.x, 0.f);                            \
                ar[q].y = fmaxf(ar[q].y + bb.y, 0.f);                            \
                ar[q].z = fmaxf(ar[q].z + bb.z, 0.f);                            \
                ar[q].w = fmaxf(ar[q].w + bb.w, 0.f);                            \
            }                                                                    \
        } else {                                                                 \
            ar[0] = ar[1] = ar[2] = ar[3] = make_float4(0.f, 0.f, 0.f, 0.f);     \
        }                                                                        \
    } while (0)

    LOAD_A(0);
    br = *(const float4*)(W + (size_t)bk * DD + n0 + bn);
    STORE_SMEM(As[0], Bs[0]);
    __syncthreads();
    #pragma unroll
    for (int ch = 0; ch < NCHUNK; ch++) {
        const int cur = ch & 1;
        if (ch + 1 < NCHUNK) {
            int kc = (ch + 1) * KC;
            LOAD_A(kc);
            br = *(const float4*)(W + (size_t)(kc + bk) * DD + n0 + bn);
        }
        GEMM_COMPUTE(As[cur], Bs[cur], mB, nB);
        if (ch + 1 < NCHUNK) {
            STORE_SMEM(As[cur ^ 1], Bs[cur ^ 1]);
            __syncthreads();
        }
    }
    #pragma unroll
    for (int rp = 0; rp < 4; rp++) {
        unsigned lo[4], hi[4];
        #pragma unroll
        for (int c = 0; c < 4; c++) UNPK_X2(lo[c], hi[c], acc2[rp][c]);
        int rlo = rows[mB + 2 * rp + 0];
        if (rlo >= 0)
            *(float4*)(xw_out + (size_t)rlo * DD + n0 + nB) =
                make_float4(__uint_as_float(lo[0]), __uint_as_float(lo[1]),
                            __uint_as_float(lo[2]), __uint_as_float(lo[3]));
        int rhi = rows[mB + 2 * rp + 1];
        if (rhi >= 0)
            *(float4*)(xw_out + (size_t)rhi * DD + n0 + nB) =
                make_float4(__uint_as_float(hi[0]), __uint_as_float(hi[1]),
                            __uint_as_float(hi[2]), __uint_as_float(hi[3]));
    }
    #undef LOAD_A
}

// ---------------- CSR gather over the compacted list --------------------------
__global__ __launch_bounds__(256) void k_gather_l(
    const float* __restrict__ xw, float* __restrict__ acc)
{
    const int w    = (blockIdx.x * 256 + threadIdx.x) >> 5;
    const int lane = threadIdx.x & 31;
    if (w >= g_nlist) return;
    const int wid = g_list[w];

    const int s = g_off[wid];
    const int e = g_off[wid + 1];
    const float4* __restrict__ xw4 = (const float4*)xw;

    const float d  = g_dis[wid];
    float4 self = xw4[(size_t)wid * 32 + lane];
    const float d2 = d * d;
    float4 a = make_float4(self.x * d2, self.y * d2, self.z * d2, self.w * d2);

    int i = s;
    for (; i + 4 <= e; i += 4) {
        int2 p0 = g_adjn[i];
        int2 p1 = g_adjn[i + 1];
        int2 p2 = g_adjn[i + 2];
        int2 p3 = g_adjn[i + 3];
        float4 v0 = xw4[(size_t)p0.x * 32 + lane];
        float4 v1 = xw4[(size_t)p1.x * 32 + lane];
        float4 v2 = xw4[(size_t)p2.x * 32 + lane];
        float4 v3 = xw4[(size_t)p3.x * 32 + lane];
        float n0 = __int_as_float(p0.y), n1 = __int_as_float(p1.y);
        float n2 = __int_as_float(p2.y), n3 = __int_as_float(p3.y);
        a.x += v0.x * n0 + v1.x * n1 + v2.x * n2 + v3.x * n3;
        a.y += v0.y * n0 + v1.y * n1 + v2.y * n2 + v3.y * n3;
        a.z += v0.z * n0 + v1.z * n1 + v2.z * n2 + v3.z * n3;
        a.w += v0.w * n0 + v1.w * n1 + v2.w * n2 + v3.w * n3;
    }
    for (; i < e; i++) {
        int2 p = g_adjn[i];
        float n = __int_as_float(p.y);
        float4 v = xw4[(size_t)p.x * 32 + lane];
        a.x += v.x * n; a.y += v.y * n; a.z += v.z * n; a.w += v.w * n;
    }
    ((float4*)acc)[(size_t)wid * 32 + lane] = a;
}

// ---------------- fused ego-gather + prediction head --------------------------
__global__ __launch_bounds__(DD) void k_predg(
    const float* __restrict__ xw, const float* __restrict__ gbias,
    const int* __restrict__ seqs, const int* __restrict__ label,
    const float* __restrict__ predW, const float* __restrict__ predB,
    float* __restrict__ out, int out_size)
{
    __shared__ float h[DD];
    __shared__ int ego_s;
    const int b = blockIdx.x, tid = threadIdx.x;
    if (tid == 0) {
        int e = seqs[b * SL];
        ego_s = ((unsigned)e < NN) ? e : 0;
    }
    __syncthreads();
    const int ego = ego_s;

    const int s = g_off[ego];
    const int e = g_off[ego + 1];
    const float d = g_dis[ego];
    float a = xw[(size_t)ego * DD + tid] * d * d;

    int i = s;
    for (; i + 4 <= e; i += 4) {
        int2 p0 = g_adjn[i];
        int2 p1 = g_adjn[i + 1];
        int2 p2 = g_adjn[i + 2];
        int2 p3 = g_adjn[i + 3];
        float v0 = xw[(size_t)p0.x * DD + tid];
        float v1 = xw[(size_t)p1.x * DD + tid];
        float v2 = xw[(size_t)p2.x * DD + tid];
        float v3 = xw[(size_t)p3.x * DD + tid];
        a += v0 * __int_as_float(p0.y) + v1 * __int_as_float(p1.y)
           + v2 * __int_as_float(p2.y) + v3 * __int_as_float(p3.y);
    }
    for (; i < e; i++) {
        int2 p = g_adjn[i];
        a += xw[(size_t)p.x * DD + tid] * __int_as_float(p.y);
    }

    h[tid] = fmaxf(a + gbias[tid], 0.0f);
    __syncthreads();

    if (tid < CC) {
        float s2 = predB[tid];
        #pragma unroll
        for (int k = 0; k < DD; k++) s2 += h[k] * predW[k * CC + tid];
        out[b * CC + tid] = s2;
    }
    if (tid == CC && out_size >= BB * CC + BB)
        out[BB * CC + b] = (float)label[ego];
}

// ---------------- host side ----------------------------------------------------
static bool now_capturing() {
    cudaStreamCaptureStatus s1 = cudaStreamCaptureStatusNone;
    cudaStreamCaptureStatus s2 = cudaStreamCaptureStatusNone;
    cudaError_t e1 = cudaStreamIsCapturing((cudaStream_t)0, &s1);
    cudaError_t e2 = cudaStreamIsCapturing(cudaStreamPerThread, &s2);
    if (e1 != cudaSuccess || e2 != cudaSuccess) { cudaGetLastError(); return true; }
    return s1 != cudaStreamCaptureStatusNone || s2 != cudaStreamCaptureStatusNone;
}

extern "C" void kernel_launch(void* const* d_in, const int* in_sizes, int n_in,
                              void* d_out, int out_size)
{
    const float* x         = (const float*)d_in[0];
    const int*   label     = (const int*)  d_in[1];
    const int*   seqs      = (const int*)  d_in[2];
    const int*   edge      = (const int*)  d_in[3];
    const int*   node_type = (const int*)  d_in[4];
    const float* fcW       = (const float*)d_in[5];
    const float* fcB       = (const float*)d_in[6];
    const float* gcnW      = (const float*)d_in[7];
    const float* gcnB      = (const float*)d_in[8];
    const float* predW     = (const float*)d_in[12];
    const float* predB     = (const float*)d_in[13];
    float* out = (float*)d_out;

    float *xw = 0, *accA = 0, *W0t = 0, *b0t = 0;
    int *degp = 0, *nlp = 0;
    unsigned char *f1p = 0, *f2p = 0;
    cudaGetSymbolAddress((void**)&xw,   g_xw);
    cudaGetSymbolAddress((void**)&accA, g_accA);
    cudaGetSymbolAddress((void**)&W0t,  g_W0t);
    cudaGetSymbolAddress((void**)&b0t,  g_b0t);
    cudaGetSymbolAddress((void**)&degp, g_deg);
    cudaGetSymbolAddress((void**)&nlp,  g_nlist);
    cudaGetSymbolAddress((void**)&f1p,  g_flag1);
    cudaGetSymbolAddress((void**)&f2p,  g_flag2);

    const bool capturing = now_capturing();

    static cudaStream_t s_csr = 0;
    static cudaEvent_t  eFork = 0, eCsr = 0;
    static bool tried = false;
    if (!tried && !capturing) {
        tried = true;
        if (cudaStreamCreateWithFlags(&s_csr, cudaStreamNonBlocking) != cudaSuccess) s_csr = 0;
        if (cudaEventCreateWithFlags(&eFork, cudaEventDisableTiming) != cudaSuccess) eFork = 0;
        if (cudaEventCreateWithFlags(&eCsr,  cudaEventDisableTiming) != cudaSuccess) eCsr = 0;
        cudaGetLastError();
    }
    const bool par = capturing && s_csr && eFork && eCsr;
    cudaStream_t sc = par ? s_csr : (cudaStream_t)0;

    const dim3 gemmGrid(DD / NT, (NN + MT - 1) / MT);   // (4, 391)
    const dim3 combGrid(DD / NT, TT);
    const int gatherBlocks = (NN * 32 + 255) / 256;     // worst case; excess exits

    if (par) {
        cudaEventRecord(eFork, 0);
        cudaStreamWaitEvent(s_csr, eFork, 0);
    }

    // ---- fork branch: CSR + relevance (slimmed) ----
    cudaMemsetAsync(degp, 0, NN * sizeof(int), sc);
    cudaMemsetAsync(f1p, 0, NN, sc);
    cudaMemsetAsync(f2p, 0, NN, sc);
    cudaMemsetAsync(nlp, 0, sizeof(int), sc);
    k_mark_ego<<<(BB + 255) / 256, 256, 0, sc>>>(seqs);
    k_degmark <<<(EE + 255) / 256, 256, 0, sc>>>(edge);
    k_part  <<<NSB, SB, 0, sc>>>();
    k_scanp <<<1,   SB, 0, sc>>>();
    k_off   <<<NSB, SB, 0, sc>>>();
    k_fillf <<<(EE + 255) / 256, 256, 0, sc>>>(edge);
    k_femita<<<NSB, SB, 0, sc>>>();
    if (par) cudaEventRecord(eCsr, s_csr);

    // ---- main branch: weight folding + fused FC/layer0 GEMM ----
    k_wcomb<<<combGrid, 128>>>(fcW, gcnW, W0t);
    k_bcomb<<<TT, DD>>>(fcB, gcnW, b0t);
    k_fc2<<<gemmGrid, 128>>>(x, node_type, W0t, b0t, xw);

    if (par) cudaStreamWaitEvent((cudaStream_t)0, eCsr, 0);

    // serial join: gather0 -> layer-1 GEMM -> fused ego-gather+head
    k_gather_l <<<gatherBlocks, 256>>>(xw, accA);
    k_sgemm_idx<<<gemmGrid, 128>>>(accA, gcnB, gcnW + DD * DD, xw);
    k_predg<<<BB, DD>>>(xw, gcnB + DD, seqs, label, predW, predB, out, out_size);

    if (capturing) return;

    // ---- light self-check (non-capture calls only; exits only on failure) ----
    cudaError_t esync = cudaDeviceSynchronize();
    if (esync != cudaSuccess) {
        fprintf(stderr, "HX sync error: %s\n", cudaGetErrorString(esync));
        exit(2);
    }
    static float o0[CC];
    cudaMemcpy(o0, out, CC * 4, cudaMemcpyDeviceToHost);
    float l1 = 0;
    bool finite = true;
    for (int c = 0; c < CC; c++) { l1 += fabsf(o0[c]); if (!isfinite(o0[c])) finite = false; }
    if (!finite || l1 < 1e-4f) {
        fprintf(stderr, "HX bad output l1=%g finite=%d\n", l1, finite);
        exit(2);
    }
    cudaGetLastError();
}

// round 17
// speedup vs baseline: 1.3585x; 1.1697x over previous
#include <cuda_runtime.h>
#include <math.h>
#include <cstdio>
#include <cstdlib>

// Problem constants
#define NN 50000
#define EE 600000
#define DD 128
#define TT 4
#define BB 2048
#define SL 16
#define CC 16

// SGEMM tiling
#define MT 128
#define NT 64              // output cols per block (2 x 32 sub-chunks)
#define KC 16
#define NCHUNK (DD / KC)   // 8
#define ASTRIDE (MT + 4)   // 132
#define BSTRIDE (NT + 4)   // 68

// scan config
#define SB 256
#define NSB ((NN + SB - 1) / SB)   // 196

typedef unsigned long long u64;

#define FMA_X2(d, a, b, c) \
    asm("fma.rn.f32x2 %0, %1, %2, %3;" : "=l"(d) : "l"(a), "l"(b), "l"(c))
#define DUP_X2(out, f) \
    asm("mov.b64 %0, {%1, %1};" : "=l"(out) : "r"(__float_as_int(f)))
#define UNPK_X2(lo_u, hi_u, in) \
    asm("mov.b64 {%0, %1}, %2;" : "=r"(lo_u), "=r"(hi_u) : "l"(in))

// ---------------- scratch (device globals) -----------------------------------
__device__ float g_dis[NN];
__device__ int   g_deg[NN];
__device__ int   g_off[NN + 1];
__device__ int   g_cur[NN];
__device__ int   g_part[SB];
__device__ int2  g_adjn[EE];           // {src, norm-bits}
__device__ unsigned char g_flag1[NN];  // ego nodes
__device__ unsigned char g_flag2[NN];  // egos + in-neighbor sources of egos
__device__ int   g_list[NN];
__device__ int   g_nlist;
__device__ float g_xw[NN * DD];
__device__ float g_accA[NN * DD];
__device__ float g_W0t[TT * DD * DD];
__device__ float g_b0t[TT * DD];

// ---------------- relevance marking -------------------------------------------
__global__ void k_mark_ego(const int* __restrict__ seqs) {
    int b = blockIdx.x * blockDim.x + threadIdx.x;
    if (b < BB) {
        int v = seqs[b * SL];
        if ((unsigned)v < NN) { g_flag1[v] = 1; g_flag2[v] = 1; }
    }
}

__global__ void k_degmark(const int* __restrict__ edge) {
    int e = blockIdx.x * blockDim.x + threadIdx.x;
    if (e >= EE) return;
    int v = edge[EE + e];
    if ((unsigned)v < NN) {
        atomicAdd(&g_deg[v], 1);
        if (g_flag1[v]) {
            int u = edge[e];
            if ((unsigned)u < NN) g_flag2[u] = 1;
        }
    }
}

// ---------------- hierarchical scan (CSR offsets) -----------------------------
__global__ __launch_bounds__(SB) void k_part() {
    __shared__ int sh[SB];
    int idx = blockIdx.x * SB + threadIdx.x;
    int v = (idx < NN) ? g_deg[idx] : 0;
    sh[threadIdx.x] = v;
    __syncthreads();
    for (int d = SB / 2; d > 0; d >>= 1) {
        if (threadIdx.x < d) sh[threadIdx.x] += sh[threadIdx.x + d];
        __syncthreads();
    }
    if (threadIdx.x == 0) g_part[blockIdx.x] = sh[0];
}

__global__ __launch_bounds__(SB) void k_scanp() {
    __shared__ int sh[SB];
    int tid = threadIdx.x;
    int v = (tid < NSB) ? g_part[tid] : 0;
    sh[tid] = v;
    __syncthreads();
    for (int d = 1; d < SB; d <<= 1) {
        int t = (tid >= d) ? sh[tid - d] : 0;
        __syncthreads();
        sh[tid] += t;
        __syncthreads();
    }
    if (tid < NSB) g_part[tid] = sh[tid] - v;
    if (tid == NSB - 1) g_off[NN] = sh[tid];
}

__global__ __launch_bounds__(SB) void k_off() {
    __shared__ int sh[SB];
    int tid = threadIdx.x;
    int idx = blockIdx.x * SB + tid;
    int v = (idx < NN) ? g_deg[idx] : 0;
    sh[tid] = v;
    __syncthreads();
    for (int d = 1; d < SB; d <<= 1) {
        int t = (tid >= d) ? sh[tid - d] : 0;
        __syncthreads();
        sh[tid] += t;
        __syncthreads();
    }
    if (idx < NN) {
        int o = g_part[blockIdx.x] + sh[tid] - v;
        g_off[idx] = o;
        g_cur[idx] = o;
        g_dis[idx] = rsqrtf((float)v + 1.0f);   // +1 = self loop
    }
}

// ---------------- CSR fill (only rows whose dst is relevant) ------------------
__global__ void k_fillf(const int* __restrict__ edge) {
    int e = blockIdx.x * blockDim.x + threadIdx.x;
    if (e >= EE) return;
    int v = edge[EE + e];
    if ((unsigned)v >= NN || !g_flag2[v]) return;
    int u = edge[e];
    if ((unsigned)u >= NN) return;
    int pos = atomicAdd(&g_cur[v], 1);
    float nm = g_dis[u] * g_dis[v];
    g_adjn[pos] = make_int2(u, __float_as_int(nm));
}

// ---------------- compaction: atomic append -----------------------------------
__global__ void k_femita() {
    int idx = blockIdx.x * blockDim.x + threadIdx.x;
    if (idx < NN && g_flag2[idx]) {
        int pos = atomicAdd(&g_nlist, 1);
        g_list[pos] = idx;
    }
}

// ---------------- packed-FMA inner product, 2 n-sub-chunks --------------------
#define GEMM_COMPUTE2(As_, Bs_)                                                \
    do {                                                                       \
        _Pragma("unroll")                                                      \
        for (int kk = 0; kk < KC; kk++) {                                      \
            ulonglong2 a01 = *(const ulonglong2*)&As_[kk][mB];                 \
            ulonglong2 a23 = *(const ulonglong2*)&As_[kk][mB + 4];             \
            float4 bx = *(const float4*)&Bs_[kk][nB];                          \
            float4 by = *(const float4*)&Bs_[kk][nB + 32];                     \
            u64 ap[4] = {a01.x, a01.y, a23.x, a23.y};                          \
            u64 bd[8];                                                         \
            DUP_X2(bd[0], bx.x); DUP_X2(bd[1], bx.y);                          \
            DUP_X2(bd[2], bx.z); DUP_X2(bd[3], bx.w);                          \
            DUP_X2(bd[4], by.x); DUP_X2(bd[5], by.y);                          \
            DUP_X2(bd[6], by.z); DUP_X2(bd[7], by.w);                          \
            _Pragma("unroll")                                                  \
            for (int rp = 0; rp < 4; rp++) {                                   \
                _Pragma("unroll")                                              \
                for (int c = 0; c < 4; c++) {                                  \
                    FMA_X2(acc2[0][rp][c], ap[rp], bd[c],     acc2[0][rp][c]); \
                    FMA_X2(acc2[1][rp][c], ap[rp], bd[4 + c], acc2[1][rp][c]); \
                }                                                              \
            }                                                                  \
        }                                                                      \
    } while (0)

#define STORE_SMEM2(Ab_, Bb_)                                                  \
    do {                                                                       \
        _Pragma("unroll")                                                      \
        for (int q = 0; q < 4; q++) {                                          \
            Ab_[q * 4 + 0][tid] = ar[q].x;                                     \
            Ab_[q * 4 + 1][tid] = ar[q].y;                                     \
            Ab_[q * 4 + 2][tid] = ar[q].z;                                     \
            Ab_[q * 4 + 3][tid] = ar[q].w;                                     \
        }                                                                      \
        *(float4*)&Bb_[bk][bn]      = br0;                                     \
        *(float4*)&Bb_[bk][bn + 32] = br1;                                     \
    } while (0)

#define LOAD_B(kc_)                                                            \
    do {                                                                       \
        br0 = *(const float4*)(W + (size_t)((kc_) + bk) * DD + n0 + bn);       \
        br1 = *(const float4*)(W + (size_t)((kc_) + bk) * DD + n0 + bn + 32);  \
    } while (0)

// ---------------- weight folding: W0t[t] = fcW[t] @ W0 ------------------------
__global__ __launch_bounds__(128) void k_wcomb(
    const float* __restrict__ fcW, const float* __restrict__ W0,
    float* __restrict__ W0t)
{
    __shared__ float As[2][KC][ASTRIDE];
    __shared__ float Bs[2][KC][BSTRIDE];
    const int tid = threadIdx.x;
    const int t  = blockIdx.y;
    const int n0 = blockIdx.x * NT;
    const int mB = (tid >> 3) * 8;
    const int nB = (tid & 7) * 4;
    const int bk = tid >> 3;
    const int bn = (tid & 7) * 4;

    const float* __restrict__ in = fcW + (size_t)t * DD * DD;
    const float* __restrict__ W  = W0;
    float* __restrict__ out = W0t + (size_t)t * DD * DD;

    u64 acc2[2][4][4];
    #pragma unroll
    for (int n = 0; n < 2; n++)
        #pragma unroll
        for (int rp = 0; rp < 4; rp++)
            #pragma unroll
            for (int c = 0; c < 4; c++) acc2[n][rp][c] = 0ULL;

    float4 ar[4], br0, br1;
    {
        const float4* p = (const float4*)(in + (size_t)tid * DD);
        ar[0] = p[0]; ar[1] = p[1]; ar[2] = p[2]; ar[3] = p[3];
        LOAD_B(0);
    }
    STORE_SMEM2(As[0], Bs[0]);
    __syncthreads();
    #pragma unroll
    for (int ch = 0; ch < NCHUNK; ch++) {
        const int cur = ch & 1;
        if (ch + 1 < NCHUNK) {
            int kc = (ch + 1) * KC;
            const float4* p = (const float4*)(in + (size_t)tid * DD + kc);
            ar[0] = p[0]; ar[1] = p[1]; ar[2] = p[2]; ar[3] = p[3];
            LOAD_B(kc);
        }
        GEMM_COMPUTE2(As[cur], Bs[cur]);
        if (ch + 1 < NCHUNK) {
            STORE_SMEM2(As[cur ^ 1], Bs[cur ^ 1]);
            __syncthreads();
        }
    }
    #pragma unroll
    for (int n = 0; n < 2; n++) {
        #pragma unroll
        for (int rp = 0; rp < 4; rp++) {
            unsigned lo[4], hi[4];
            #pragma unroll
            for (int c = 0; c < 4; c++) UNPK_X2(lo[c], hi[c], acc2[n][rp][c]);
            *(float4*)(out + (size_t)(mB + 2 * rp + 0) * DD + n0 + n * 32 + nB) =
                make_float4(__uint_as_float(lo[0]), __uint_as_float(lo[1]),
                            __uint_as_float(lo[2]), __uint_as_float(lo[3]));
            *(float4*)(out + (size_t)(mB + 2 * rp + 1) * DD + n0 + n * 32 + nB) =
                make_float4(__uint_as_float(hi[0]), __uint_as_float(hi[1]),
                            __uint_as_float(hi[2]), __uint_as_float(hi[3]));
        }
    }
}

__global__ __launch_bounds__(DD) void k_bcomb(
    const float* __restrict__ fcB, const float* __restrict__ W0,
    float* __restrict__ b0t)
{
    __shared__ float b[DD];
    const int t = blockIdx.x, j = threadIdx.x;
    b[j] = fcB[t * DD + j];
    __syncthreads();
    float s = 0.f;
    #pragma unroll 8
    for (int i = 0; i < DD; i++) s += b[i] * W0[i * DD + j];
    b0t[t * DD + j] = s;
}

// ---------------- fused FC+layer0 GEMM (NT=64, double-buffered) ---------------
__global__ __launch_bounds__(128) void k_fc2(
    const float* __restrict__ x, const int* __restrict__ node_type,
    const float* __restrict__ W0t, const float* __restrict__ b0t,
    float* __restrict__ xw_out)
{
    __shared__ float As[2][KC][ASTRIDE];
    __shared__ float Bs[2][KC][BSTRIDE];
    const int tid = threadIdx.x;
    const int m0 = blockIdx.y * MT;
    const int n0 = blockIdx.x * NT;
    const int mB = (tid >> 3) * 8;
    const int nB = (tid & 7) * 4;
    const int  mload  = m0 + tid;
    const bool mvalid = (mload < NN);
    const int  bk = tid >> 3;
    const int  bn = (tid & 7) * 4;

    int t0 = node_type[m0];
    int mlast = m0 + MT - 1; if (mlast >= NN) mlast = NN - 1;
    int t1 = node_type[mlast];
    if ((unsigned)t0 >= TT) t0 = 0;
    if ((unsigned)t1 >= TT) t1 = TT - 1;

    float4 ar[4], br0, br1;

    for (int t = t0; t <= t1; t++) {
        const float* __restrict__ W = W0t + (size_t)t * DD * DD;

        u64 acc2[2][4][4];
        #pragma unroll
        for (int n = 0; n < 2; n++)
            #pragma unroll
            for (int rp = 0; rp < 4; rp++)
                #pragma unroll
                for (int c = 0; c < 4; c++) acc2[n][rp][c] = 0ULL;

        if (mvalid) {
            const float4* p = (const float4*)(x + (size_t)mload * DD);
            ar[0] = p[0]; ar[1] = p[1]; ar[2] = p[2]; ar[3] = p[3];
        } else {
            ar[0] = ar[1] = ar[2] = ar[3] = make_float4(0.f, 0.f, 0.f, 0.f);
        }
        LOAD_B(0);
        STORE_SMEM2(As[0], Bs[0]);
        __syncthreads();

        #pragma unroll
        for (int ch = 0; ch < NCHUNK; ch++) {
            const int cur = ch & 1;
            if (ch + 1 < NCHUNK) {
                int kc = (ch + 1) * KC;
                if (mvalid) {
                    const float4* p = (const float4*)(x + (size_t)mload * DD + kc);
                    ar[0] = p[0]; ar[1] = p[1]; ar[2] = p[2]; ar[3] = p[3];
                }
                LOAD_B(kc);
            }
            GEMM_COMPUTE2(As[cur], Bs[cur]);
            if (ch + 1 < NCHUNK) {
                STORE_SMEM2(As[cur ^ 1], Bs[cur ^ 1]);
                __syncthreads();
            }
        }

        #pragma unroll
        for (int n = 0; n < 2; n++) {
            const float4 fb = *(const float4*)(b0t + (size_t)t * DD + n0 + n * 32 + nB);
            #pragma unroll
            for (int rp = 0; rp < 4; rp++) {
                unsigned lo[4], hi[4];
                #pragma unroll
                for (int c = 0; c < 4; c++) UNPK_X2(lo[c], hi[c], acc2[n][rp][c]);
                int mlo = m0 + mB + 2 * rp;
                if (mlo < NN && node_type[mlo] == t)
                    *(float4*)(xw_out + (size_t)mlo * DD + n0 + n * 32 + nB) =
                        make_float4(__uint_as_float(lo[0]) + fb.x,
                                    __uint_as_float(lo[1]) + fb.y,
                                    __uint_as_float(lo[2]) + fb.z,
                                    __uint_as_float(lo[3]) + fb.w);
                int mhi = mlo + 1;
                if (mhi < NN && node_type[mhi] == t)
                    *(float4*)(xw_out + (size_t)mhi * DD + n0 + n * 32 + nB) =
                        make_float4(__uint_as_float(hi[0]) + fb.x,
                                    __uint_as_float(hi[1]) + fb.y,
                                    __uint_as_float(hi[2]) + fb.z,
                                    __uint_as_float(hi[3]) + fb.w);
            }
        }
        __syncthreads();  // protect smem before next type pass restores buf 0
    }
}

// ---------------- layer-1 GEMM over COMPACTED rows (NT=64) --------------------
__global__ __launch_bounds__(128) void k_sgemm_idx(
    const float* __restrict__ in, const float* __restrict__ bias,
    const float* __restrict__ W, float* __restrict__ xw_out)
{
    const int nlist = g_nlist;
    const int m0 = blockIdx.y * MT;
    if (m0 >= nlist) return;

    __shared__ float As[2][KC][ASTRIDE];
    __shared__ float Bs[2][KC][BSTRIDE];
    __shared__ int   rows[MT];
    const int tid = threadIdx.x;
    const int n0 = blockIdx.x * NT;
    const int mB = (tid >> 3) * 8;
    const int nB = (tid & 7) * 4;
    const int bk = tid >> 3;
    const int bn = (tid & 7) * 4;

    int myrow = -1;
    if (m0 + tid < nlist) myrow = g_list[m0 + tid];
    rows[tid] = myrow;
    const bool mvalid = (myrow >= 0);

    u64 acc2[2][4][4];
    #pragma unroll
    for (int n = 0; n < 2; n++)
        #pragma unroll
        for (int rp = 0; rp < 4; rp++)
            #pragma unroll
            for (int c = 0; c < 4; c++) acc2[n][rp][c] = 0ULL;

    float4 ar[4], br0, br1;

    #define LOAD_A(kc_) do {                                                     \
        if (mvalid) {                                                            \
            const float4* _p = (const float4*)(in + (size_t)myrow * DD + (kc_)); \
            ar[0] = _p[0]; ar[1] = _p[1]; ar[2] = _p[2]; ar[3] = _p[3];          \
            _Pragma("unroll")                                                    \
            for (int q = 0; q < 4; q++) {                                        \
                float4 bb = *(const float4*)(bias + (kc_) + q * 4);              \
                ar[q].x = fmaxf(ar[q].x + bb.x, 0.f);                            \
                ar[q].y = fmaxf(ar[q].y + bb.y, 0.f);                            \
                ar[q].z = fmaxf(ar[q].z + bb.z, 0.f);                            \
                ar[q].w = fmaxf(ar[q].w + bb.w, 0.f);                            \
            }                                                                    \
        } else {                                                                 \
            ar[0] = ar[1] = ar[2] = ar[3] = make_float4(0.f, 0.f, 0.f, 0.f);     \
        }                                                                        \
    } while (0)

    LOAD_A(0);
    LOAD_B(0);
    STORE_SMEM2(As[0], Bs[0]);
    __syncthreads();
    #pragma unroll
    for (int ch = 0; ch < NCHUNK; ch++) {
        const int cur = ch & 1;
        if (ch + 1 < NCHUNK) {
            int kc = (ch + 1) * KC;
            LOAD_A(kc);
            LOAD_B(kc);
        }
        GEMM_COMPUTE2(As[cur], Bs[cur]);
        if (ch + 1 < NCHUNK) {
            STORE_SMEM2(As[cur ^ 1], Bs[cur ^ 1]);
            __syncthreads();
        }
    }
    #pragma unroll
    for (int n = 0; n < 2; n++) {
        #pragma unroll
        for (int rp = 0; rp < 4; rp++) {
            unsigned lo[4], hi[4];
            #pragma unroll
            for (int c = 0; c < 4; c++) UNPK_X2(lo[c], hi[c], acc2[n][rp][c]);
            int rlo = rows[mB + 2 * rp + 0];
            if (rlo >= 0)
                *(float4*)(xw_out + (size_t)rlo * DD + n0 + n * 32 + nB) =
                    make_float4(__uint_as_float(lo[0]), __uint_as_float(lo[1]),
                                __uint_as_float(lo[2]), __uint_as_float(lo[3]));
            int rhi = rows[mB + 2 * rp + 1];
            if (rhi >= 0)
                *(float4*)(xw_out + (size_t)rhi * DD + n0 + n * 32 + nB) =
                    make_float4(__uint_as_float(hi[0]), __uint_as_float(hi[1]),
                                __uint_as_float(hi[2]), __uint_as_float(hi[3]));
        }
    }
    #undef LOAD_A
}

// ---------------- CSR gather over the compacted list --------------------------
__global__ __launch_bounds__(256) void k_gather_l(
    const float* __restrict__ xw, float* __restrict__ acc)
{
    const int w    = (blockIdx.x * 256 + threadIdx.x) >> 5;
    const int lane = threadIdx.x & 31;
    if (w >= g_nlist) return;
    const int wid = g_list[w];

    const int s = g_off[wid];
    const int e = g_off[wid + 1];
    const float4* __restrict__ xw4 = (const float4*)xw;

    const float d  = g_dis[wid];
    float4 self = xw4[(size_t)wid * 32 + lane];
    const float d2 = d * d;
    float4 a = make_float4(self.x * d2, self.y * d2, self.z * d2, self.w * d2);

    int i = s;
    for (; i + 4 <= e; i += 4) {
        int2 p0 = g_adjn[i];
        int2 p1 = g_adjn[i + 1];
        int2 p2 = g_adjn[i + 2];
        int2 p3 = g_adjn[i + 3];
        float4 v0 = xw4[(size_t)p0.x * 32 + lane];
        float4 v1 = xw4[(size_t)p1.x * 32 + lane];
        float4 v2 = xw4[(size_t)p2.x * 32 + lane];
        float4 v3 = xw4[(size_t)p3.x * 32 + lane];
        float n0 = __int_as_float(p0.y), n1 = __int_as_float(p1.y);
        float n2 = __int_as_float(p2.y), n3 = __int_as_float(p3.y);
        a.x += v0.x * n0 + v1.x * n1 + v2.x * n2 + v3.x * n3;
        a.y += v0.y * n0 + v1.y * n1 + v2.y * n2 + v3.y * n3;
        a.z += v0.z * n0 + v1.z * n1 + v2.z * n2 + v3.z * n3;
        a.w += v0.w * n0 + v1.w * n1 + v2.w * n2 + v3.w * n3;
    }
    for (; i < e; i++) {
        int2 p = g_adjn[i];
        float n = __int_as_float(p.y);
        float4 v = xw4[(size_t)p.x * 32 + lane];
        a.x += v.x * n; a.y += v.y * n; a.z += v.z * n; a.w += v.w * n;
    }
    ((float4*)acc)[(size_t)wid * 32 + lane] = a;
}

// ---------------- fused ego-gather + prediction head --------------------------
__global__ __launch_bounds__(DD) void k_predg(
    const float* __restrict__ xw, const float* __restrict__ gbias,
    const int* __restrict__ seqs, const int* __restrict__ label,
    const float* __restrict__ predW, const float* __restrict__ predB,
    float* __restrict__ out, int out_size)
{
    __shared__ float h[DD];
    __shared__ int ego_s;
    const int b = blockIdx.x, tid = threadIdx.x;
    if (tid == 0) {
        int e = seqs[b * SL];
        ego_s = ((unsigned)e < NN) ? e : 0;
    }
    __syncthreads();
    const int ego = ego_s;

    const int s = g_off[ego];
    const int e = g_off[ego + 1];
    const float d = g_dis[ego];
    float a = xw[(size_t)ego * DD + tid] * d * d;

    int i = s;
    for (; i + 4 <= e; i += 4) {
        int2 p0 = g_adjn[i];
        int2 p1 = g_adjn[i + 1];
        int2 p2 = g_adjn[i + 2];
        int2 p3 = g_adjn[i + 3];
        float v0 = xw[(size_t)p0.x * DD + tid];
        float v1 = xw[(size_t)p1.x * DD + tid];
        float v2 = xw[(size_t)p2.x * DD + tid];
        float v3 = xw[(size_t)p3.x * DD + tid];
        a += v0 * __int_as_float(p0.y) + v1 * __int_as_float(p1.y)
           + v2 * __int_as_float(p2.y) + v3 * __int_as_float(p3.y);
    }
    for (; i < e; i++) {
        int2 p = g_adjn[i];
        a += xw[(size_t)p.x * DD + tid] * __int_as_float(p.y);
    }

    h[tid] = fmaxf(a + gbias[tid], 0.0f);
    __syncthreads();

    if (tid < CC) {
        float s2 = predB[tid];
        #pragma unroll
        for (int k = 0; k < DD; k++) s2 += h[k] * predW[k * CC + tid];
        out[b * CC + tid] = s2;
    }
    if (tid == CC && out_size >= BB * CC + BB)
        out[BB * CC + b] = (float)label[ego];
}

// ---------------- host side ----------------------------------------------------
static bool now_capturing() {
    cudaStreamCaptureStatus s1 = cudaStreamCaptureStatusNone;
    cudaStreamCaptureStatus s2 = cudaStreamCaptureStatusNone;
    cudaError_t e1 = cudaStreamIsCapturing((cudaStream_t)0, &s1);
    cudaError_t e2 = cudaStreamIsCapturing(cudaStreamPerThread, &s2);
    if (e1 != cudaSuccess || e2 != cudaSuccess) { cudaGetLastError(); return true; }
    return s1 != cudaStreamCaptureStatusNone || s2 != cudaStreamCaptureStatusNone;
}

extern "C" void kernel_launch(void* const* d_in, const int* in_sizes, int n_in,
                              void* d_out, int out_size)
{
    const float* x         = (const float*)d_in[0];
    const int*   label     = (const int*)  d_in[1];
    const int*   seqs      = (const int*)  d_in[2];
    const int*   edge      = (const int*)  d_in[3];
    const int*   node_type = (const int*)  d_in[4];
    const float* fcW       = (const float*)d_in[5];
    const float* fcB       = (const float*)d_in[6];
    const float* gcnW      = (const float*)d_in[7];
    const float* gcnB      = (const float*)d_in[8];
    const float* predW     = (const float*)d_in[12];
    const float* predB     = (const float*)d_in[13];
    float* out = (float*)d_out;

    float *xw = 0, *accA = 0, *W0t = 0, *b0t = 0;
    int *degp = 0, *nlp = 0;
    unsigned char *f1p = 0, *f2p = 0;
    cudaGetSymbolAddress((void**)&xw,   g_xw);
    cudaGetSymbolAddress((void**)&accA, g_accA);
    cudaGetSymbolAddress((void**)&W0t,  g_W0t);
    cudaGetSymbolAddress((void**)&b0t,  g_b0t);
    cudaGetSymbolAddress((void**)&degp, g_deg);
    cudaGetSymbolAddress((void**)&nlp,  g_nlist);
    cudaGetSymbolAddress((void**)&f1p,  g_flag1);
    cudaGetSymbolAddress((void**)&f2p,  g_flag2);

    const bool capturing = now_capturing();

    static cudaStream_t s_csr = 0;
    static cudaEvent_t  eFork = 0, eCsr = 0;
    static bool tried = false;
    if (!tried && !capturing) {
        tried = true;
        if (cudaStreamCreateWithFlags(&s_csr, cudaStreamNonBlocking) != cudaSuccess) s_csr = 0;
        if (cudaEventCreateWithFlags(&eFork, cudaEventDisableTiming) != cudaSuccess) eFork = 0;
        if (cudaEventCreateWithFlags(&eCsr,  cudaEventDisableTiming) != cudaSuccess) eCsr = 0;
        cudaGetLastError();
    }
    const bool par = capturing && s_csr && eFork && eCsr;
    cudaStream_t sc = par ? s_csr : (cudaStream_t)0;

    const dim3 gemmGrid(DD / NT, (NN + MT - 1) / MT);   // (2, 391)
    const dim3 combGrid(DD / NT, TT);                   // (2, 4)
    const int gatherBlocks = (NN * 32 + 255) / 256;

    if (par) {
        cudaEventRecord(eFork, 0);
        cudaStreamWaitEvent(s_csr, eFork, 0);
    }

    // ---- fork branch: CSR + relevance (slimmed) ----
    cudaMemsetAsync(degp, 0, NN * sizeof(int), sc);
    cudaMemsetAsync(f1p, 0, NN, sc);
    cudaMemsetAsync(f2p, 0, NN, sc);
    cudaMemsetAsync(nlp, 0, sizeof(int), sc);
    k_mark_ego<<<(BB + 255) / 256, 256, 0, sc>>>(seqs);
    k_degmark <<<(EE + 255) / 256, 256, 0, sc>>>(edge);
    k_part  <<<NSB, SB, 0, sc>>>();
    k_scanp <<<1,   SB, 0, sc>>>();
    k_off   <<<NSB, SB, 0, sc>>>();
    k_fillf <<<(EE + 255) / 256, 256, 0, sc>>>(edge);
    k_femita<<<NSB, SB, 0, sc>>>();
    if (par) cudaEventRecord(eCsr, s_csr);

    // ---- main branch: weight folding + fused FC/layer0 GEMM ----
    k_wcomb<<<combGrid, 128>>>(fcW, gcnW, W0t);
    k_bcomb<<<TT, DD>>>(fcB, gcnW, b0t);
    k_fc2<<<gemmGrid, 128>>>(x, node_type, W0t, b0t, xw);

    if (par) cudaStreamWaitEvent((cudaStream_t)0, eCsr, 0);

    // serial join: gather0 -> layer-1 GEMM -> fused ego-gather+head
    k_gather_l <<<gatherBlocks, 256>>>(xw, accA);
    k_sgemm_idx<<<gemmGrid, 128>>>(accA, gcnB, gcnW + DD * DD, xw);
    k_predg<<<BB, DD>>>(xw, gcnB + DD, seqs, label, predW, predB, out, out_size);

    if (capturing) return;

    // ---- light self-check (non-capture calls only; exits only on failure) ----
    cudaError_t esync = cudaDeviceSynchronize();
    if (esync != cudaSuccess) {
        fprintf(stderr, "HX sync error: %s\n", cudaGetErrorString(esync));
        exit(2);
    }
    static float o0[CC];
    cudaMemcpy(o0, out, CC * 4, cudaMemcpyDeviceToHost);
    float l1 = 0;
    bool finite = true;
    for (int c = 0; c < CC; c++) { l1 += fabsf(o0[c]); if (!isfinite(o0[c])) finite = false; }
    if (!finite || l1 < 1e-4f) {
        fprintf(stderr, "HX bad output l1=%g finite=%d\n", l1, finite);
        exit(2);
    }
    cudaGetLastError();
}